// round 1
// baseline (speedup 1.0000x reference)
#include <cuda_runtime.h>
#include <math.h>
#include <float.h>

#define DIM 2048
#define NHEADS 16
#define NKV 4
#define HD 128
#define BATCH 2
#define SEQ 2048
#define BT (BATCH*SEQ)     // 4096 rows
#define KVDIM (NKV*HD)     // 512

// Scratch (allocation-free rule: __device__ globals)
__device__ float g_q[(size_t)BT*DIM];
__device__ float g_k[(size_t)BT*KVDIM];
__device__ float g_v[(size_t)BT*KVDIM];
__device__ float g_y[(size_t)BT*DIM];

// ---------------------------------------------------------------------------
// Tiled SGEMM: C[M,N] = A[M,K] @ B[N,K]^T   (A,B,C row-major)
// BM=BN=128, BK=16, 256 threads, 8x8 per-thread tile.
// All dims here are multiples of the tile sizes (no bounds checks).
// ---------------------------------------------------------------------------
__global__ __launch_bounds__(256) void sgemm_nt(const float* __restrict__ A,
                                                const float* __restrict__ B,
                                                float* __restrict__ C,
                                                int M, int N, int K)
{
    __shared__ float As[16][128];
    __shared__ float Bs[16][128];
    const int tid = threadIdx.x;
    const int tx = tid & 15;
    const int ty = tid >> 4;
    const int row0 = blockIdx.y * 128;
    const int col0 = blockIdx.x * 128;

    float acc[8][8];
#pragma unroll
    for (int i = 0; i < 8; i++)
#pragma unroll
        for (int j = 0; j < 8; j++) acc[i][j] = 0.f;

    for (int k0 = 0; k0 < K; k0 += 16) {
        // Load 128x16 A tile (transposed into As[k][m]) : 512 float4, 2/thread
#pragma unroll
        for (int i = 0; i < 2; i++) {
            int f = tid + i * 256;      // 0..511
            int r = f >> 2;             // 0..127
            int c4 = f & 3;             // 0..3
            float4 v = *(const float4*)&A[(size_t)(row0 + r) * K + k0 + c4 * 4];
            As[c4 * 4 + 0][r] = v.x;
            As[c4 * 4 + 1][r] = v.y;
            As[c4 * 4 + 2][r] = v.z;
            As[c4 * 4 + 3][r] = v.w;
        }
#pragma unroll
        for (int i = 0; i < 2; i++) {
            int f = tid + i * 256;
            int r = f >> 2;
            int c4 = f & 3;
            float4 v = *(const float4*)&B[(size_t)(col0 + r) * K + k0 + c4 * 4];
            Bs[c4 * 4 + 0][r] = v.x;
            Bs[c4 * 4 + 1][r] = v.y;
            Bs[c4 * 4 + 2][r] = v.z;
            Bs[c4 * 4 + 3][r] = v.w;
        }
        __syncthreads();

#pragma unroll
        for (int kk = 0; kk < 16; kk++) {
            float4 a0 = *(float4*)&As[kk][ty * 8];
            float4 a1 = *(float4*)&As[kk][ty * 8 + 4];
            float4 b0 = *(float4*)&Bs[kk][tx * 8];
            float4 b1 = *(float4*)&Bs[kk][tx * 8 + 4];
            float a[8] = {a0.x, a0.y, a0.z, a0.w, a1.x, a1.y, a1.z, a1.w};
            float b[8] = {b0.x, b0.y, b0.z, b0.w, b1.x, b1.y, b1.z, b1.w};
#pragma unroll
            for (int i = 0; i < 8; i++)
#pragma unroll
                for (int j = 0; j < 8; j++)
                    acc[i][j] += a[i] * b[j];
        }
        __syncthreads();
    }

#pragma unroll
    for (int i = 0; i < 8; i++) {
        size_t off = (size_t)(row0 + ty * 8 + i) * N + col0 + tx * 8;
        float4 c0 = make_float4(acc[i][0], acc[i][1], acc[i][2], acc[i][3]);
        float4 c1 = make_float4(acc[i][4], acc[i][5], acc[i][6], acc[i][7]);
        *(float4*)&C[off] = c0;
        *(float4*)&C[off + 4] = c1;
    }
}

// ---------------------------------------------------------------------------
// Fused RMSNorm (per head, 128 elems) + RoPE + q_gain, in-place on g_q / g_k.
// grid = (BT, NHEADS+NKV), block = 64 threads (one thread per rotary pair).
// ---------------------------------------------------------------------------
__global__ void norm_rope_kernel(const float* __restrict__ q_gain)
{
    const int row = blockIdx.x;        // 0..BT-1
    int h = blockIdx.y;                // 0..19
    const int j = threadIdx.x;         // 0..63

    float* buf;
    int ld;
    float gain = 1.f;
    if (h < NHEADS) {
        buf = g_q; ld = DIM; gain = q_gain[h];
    } else {
        buf = g_k; ld = KVDIM; h -= NHEADS;
    }
    float* p = buf + (size_t)row * ld + h * HD;

    float x1 = p[j];
    float x2 = p[j + 64];
    float ss = x1 * x1 + x2 * x2;
#pragma unroll
    for (int o = 16; o; o >>= 1) ss += __shfl_xor_sync(0xffffffffu, ss, o);
    __shared__ float s2[2];
    if ((j & 31) == 0) s2[j >> 5] = ss;
    __syncthreads();
    ss = s2[0] + s2[1];

    float r = rsqrtf(ss * (1.0f / 128.0f) + 1.1920928955078125e-07f);
    x1 *= r; x2 *= r;

    const int t = row % SEQ;
    // inv_freq = 10000^(-j/64); ln(10000) = 9.210340371976184
    float inv_freq = expf(-(float)j * (9.210340371976184f / 64.0f));
    float ang = (float)t * inv_freq;
    float sn, cs;
    sincosf(ang, &sn, &cs);

    float y1 = (x1 * cs + x2 * sn) * gain;
    float y2 = (-x1 * sn + x2 * cs) * gain;
    p[j] = y1;
    p[j + 64] = y2;
}

// ---------------------------------------------------------------------------
// Flash attention (fp32), causal. One block per (q-tile of 64 rows, b*h).
// 256 threads; per-thread: 4 S-rows x 4 S-cols, 4 O-rows x 8 O-cols.
// ---------------------------------------------------------------------------
#define QSTR 68   // padded smem stride for transposed Q/K and P (16B aligned)

__global__ __launch_bounds__(256) void attn_kernel()
{
    extern __shared__ float sm[];
    float* Qts = sm;                      // [128][QSTR]  (d-major, transposed)
    float* Kts = Qts + 128 * QSTR;        // [128][QSTR]
    float* Vs  = Kts + 128 * QSTR;        // [64][128]
    float* Ps  = Vs + 64 * 128;           // [64][QSTR]

    const int qt = blockIdx.x;            // 0..SEQ/64-1
    const int bh = blockIdx.y;            // 0..31
    const int b = bh >> 4;
    const int h = bh & 15;
    const int kvh = h >> 2;
    const int tid = threadIdx.x;
    const int tx = tid & 15;
    const int ty = tid >> 4;

    const float scale = 0.08838834764831845f; // 1/sqrt(128)
    const int qbase = qt * 64;

    // Load Q tile (64 x 128), transposed + pre-scaled
    const float* Qg = g_q + ((size_t)(b * SEQ + qbase)) * DIM + h * HD;
#pragma unroll
    for (int i = 0; i < 8; i++) {
        int f = tid + i * 256;       // 0..2047 (float4 units)
        int r = f >> 5;              // 0..63
        int c4 = f & 31;             // 0..31
        float4 v = *(const float4*)&Qg[(size_t)r * DIM + c4 * 4];
        Qts[(c4 * 4 + 0) * QSTR + r] = v.x * scale;
        Qts[(c4 * 4 + 1) * QSTR + r] = v.y * scale;
        Qts[(c4 * 4 + 2) * QSTR + r] = v.z * scale;
        Qts[(c4 * 4 + 3) * QSTR + r] = v.w * scale;
    }

    float m[4], l[4], o[4][8];
#pragma unroll
    for (int i = 0; i < 4; i++) {
        m[i] = -FLT_MAX;
        l[i] = 0.f;
#pragma unroll
        for (int j = 0; j < 8; j++) o[i][j] = 0.f;
    }
    __syncthreads();

    for (int kt = 0; kt <= qt; kt++) {
        const int kbase = kt * 64;
        const float* Kg = g_k + ((size_t)(b * SEQ + kbase)) * KVDIM + kvh * HD;
        const float* Vg = g_v + ((size_t)(b * SEQ + kbase)) * KVDIM + kvh * HD;

        // Load K tile (transposed) and V tile (row-major)
#pragma unroll
        for (int i = 0; i < 8; i++) {
            int f = tid + i * 256;
            int r = f >> 5;
            int c4 = f & 31;
            float4 kv = *(const float4*)&Kg[(size_t)r * KVDIM + c4 * 4];
            Kts[(c4 * 4 + 0) * QSTR + r] = kv.x;
            Kts[(c4 * 4 + 1) * QSTR + r] = kv.y;
            Kts[(c4 * 4 + 2) * QSTR + r] = kv.z;
            Kts[(c4 * 4 + 3) * QSTR + r] = kv.w;
            float4 vv = *(const float4*)&Vg[(size_t)r * KVDIM + c4 * 4];
            *(float4*)&Vs[r * 128 + c4 * 4] = vv;
        }
        __syncthreads();

        // S = Q K^T  (64x64, per-thread 4x4)
        float s[4][4];
#pragma unroll
        for (int i = 0; i < 4; i++)
#pragma unroll
            for (int j = 0; j < 4; j++) s[i][j] = 0.f;

#pragma unroll 8
        for (int k = 0; k < 128; k++) {
            float4 a = *(float4*)&Qts[k * QSTR + ty * 4];
            float4 bb = *(float4*)&Kts[k * QSTR + tx * 4];
            float av[4] = {a.x, a.y, a.z, a.w};
            float bv[4] = {bb.x, bb.y, bb.z, bb.w};
#pragma unroll
            for (int i = 0; i < 4; i++)
#pragma unroll
                for (int j = 0; j < 4; j++)
                    s[i][j] += av[i] * bv[j];
        }

        // Causal mask on diagonal tile
        if (kt == qt) {
#pragma unroll
            for (int i = 0; i < 4; i++)
#pragma unroll
                for (int j = 0; j < 4; j++)
                    if (kbase + tx * 4 + j > qbase + ty * 4 + i)
                        s[i][j] = -FLT_MAX;
        }

        // Online softmax (per row; 16 lanes share a row)
#pragma unroll
        for (int i = 0; i < 4; i++) {
            float mt = fmaxf(fmaxf(s[i][0], s[i][1]), fmaxf(s[i][2], s[i][3]));
#pragma unroll
            for (int off = 1; off < 16; off <<= 1)
                mt = fmaxf(mt, __shfl_xor_sync(0xffffffffu, mt, off));
            float mnew = fmaxf(m[i], mt);
            float alpha = __expf(m[i] - mnew);
            float p0 = __expf(s[i][0] - mnew);
            float p1 = __expf(s[i][1] - mnew);
            float p2 = __expf(s[i][2] - mnew);
            float p3 = __expf(s[i][3] - mnew);
            float lsum = p0 + p1 + p2 + p3;
#pragma unroll
            for (int off = 1; off < 16; off <<= 1)
                lsum += __shfl_xor_sync(0xffffffffu, lsum, off);
            l[i] = l[i] * alpha + lsum;
            m[i] = mnew;
#pragma unroll
            for (int j = 0; j < 8; j++) o[i][j] *= alpha;
            *(float4*)&Ps[(ty * 4 + i) * QSTR + tx * 4] = make_float4(p0, p1, p2, p3);
        }
        __syncthreads();

        // O += P V  (per-thread 4 rows x 8 cols)
#pragma unroll 4
        for (int kk = 0; kk < 64; kk++) {
            float p0 = Ps[(ty * 4 + 0) * QSTR + kk];
            float p1 = Ps[(ty * 4 + 1) * QSTR + kk];
            float p2 = Ps[(ty * 4 + 2) * QSTR + kk];
            float p3 = Ps[(ty * 4 + 3) * QSTR + kk];
            float4 v0 = *(float4*)&Vs[kk * 128 + tx * 8];
            float4 v1 = *(float4*)&Vs[kk * 128 + tx * 8 + 4];
            float vv[8] = {v0.x, v0.y, v0.z, v0.w, v1.x, v1.y, v1.z, v1.w};
#pragma unroll
            for (int j = 0; j < 8; j++) {
                o[0][j] += p0 * vv[j];
                o[1][j] += p1 * vv[j];
                o[2][j] += p2 * vv[j];
                o[3][j] += p3 * vv[j];
            }
        }
        __syncthreads();
    }

    // Epilogue: normalize and write y (row-major (B*T, DIM), head-sliced)
    float* Yg = g_y + ((size_t)(b * SEQ + qbase)) * DIM + h * HD;
#pragma unroll
    for (int i = 0; i < 4; i++) {
        float inv = 1.0f / l[i];
        int r = ty * 4 + i;
        float4 y0 = make_float4(o[i][0] * inv, o[i][1] * inv, o[i][2] * inv, o[i][3] * inv);
        float4 y1 = make_float4(o[i][4] * inv, o[i][5] * inv, o[i][6] * inv, o[i][7] * inv);
        *(float4*)&Yg[(size_t)r * DIM + tx * 8] = y0;
        *(float4*)&Yg[(size_t)r * DIM + tx * 8 + 4] = y1;
    }
}

// ---------------------------------------------------------------------------
extern "C" void kernel_launch(void* const* d_in, const int* in_sizes, int n_in,
                              void* d_out, int out_size)
{
    (void)in_sizes; (void)n_in; (void)out_size;
    const float* x  = (const float*)d_in[0];
    const float* qg = (const float*)d_in[1];
    const float* Wq = (const float*)d_in[2];
    const float* Wk = (const float*)d_in[3];
    const float* Wv = (const float*)d_in[4];
    const float* Wp = (const float*)d_in[5];
    float* out = (float*)d_out;

    float *qp, *kp, *vp, *yp;
    cudaGetSymbolAddress((void**)&qp, g_q);
    cudaGetSymbolAddress((void**)&kp, g_k);
    cudaGetSymbolAddress((void**)&vp, g_v);
    cudaGetSymbolAddress((void**)&yp, g_y);

    // QKV projections
    sgemm_nt<<<dim3(DIM / 128, BT / 128), 256>>>(x, Wq, qp, BT, DIM, DIM);
    sgemm_nt<<<dim3(KVDIM / 128, BT / 128), 256>>>(x, Wk, kp, BT, KVDIM, DIM);
    sgemm_nt<<<dim3(KVDIM / 128, BT / 128), 256>>>(x, Wv, vp, BT, KVDIM, DIM);

    // RMSNorm + RoPE + gain (q and k)
    norm_rope_kernel<<<dim3(BT, NHEADS + NKV), 64>>>(qg);

    // Flash attention
    size_t smem = (size_t)(2 * 128 * QSTR + 64 * 128 + 64 * QSTR) * sizeof(float);
    cudaFuncSetAttribute(attn_kernel, cudaFuncAttributeMaxDynamicSharedMemorySize,
                         (int)smem);
    attn_kernel<<<dim3(SEQ / 64, BATCH * NHEADS), 256, smem>>>();

    // Output projection
    sgemm_nt<<<dim3(DIM / 128, BT / 128), 256>>>(yp, Wp, out, BT, DIM, DIM);
}

// round 2
// speedup vs baseline: 3.8949x; 3.8949x over previous
#include <cuda_runtime.h>
#include <math.h>
#include <float.h>
#include <stdint.h>

#define DIM 2048
#define NHEADS 16
#define NKV 4
#define HD 128
#define BATCH 2
#define SEQ 2048
#define BT (BATCH*SEQ)     // 4096
#define KVDIM (NKV*HD)     // 512

// Scratch (__device__ globals per allocation-free rule)
__device__ __align__(16) float g_q[(size_t)BT*DIM];
__device__ __align__(16) float g_k[(size_t)BT*KVDIM];
__device__ __align__(16) float g_v[(size_t)BT*KVDIM];
__device__ __align__(16) float g_y[(size_t)BT*DIM];
__device__ __align__(16) float g_xr[(size_t)BT*DIM];
__device__ __align__(16) float g_wq[(size_t)DIM*DIM];
__device__ __align__(16) float g_wk[(size_t)KVDIM*DIM];
__device__ __align__(16) float g_wv[(size_t)KVDIM*DIM];
__device__ __align__(16) float g_wp[(size_t)DIM*DIM];
__device__ __align__(16) float2 g_tab[SEQ*64];

// ---------------------------------------------------------------------------
// helpers
// ---------------------------------------------------------------------------
__device__ __forceinline__ uint32_t f2tf(float x) {
    uint32_t u;
    asm("cvt.rna.tf32.f32 %0, %1;" : "=r"(u) : "f"(x));
    return u;
}
__device__ __forceinline__ float f2tff(float x) { return __uint_as_float(f2tf(x)); }

__device__ __forceinline__ void mma_tf32(float4& c, uint32_t a0, uint32_t a1,
                                         uint32_t a2, uint32_t a3,
                                         uint32_t b0, uint32_t b1) {
    asm volatile(
        "mma.sync.aligned.m16n8k8.row.col.f32.tf32.tf32.f32 "
        "{%0,%1,%2,%3}, {%4,%5,%6,%7}, {%8,%9}, {%0,%1,%2,%3};"
        : "+f"(c.x), "+f"(c.y), "+f"(c.z), "+f"(c.w)
        : "r"(a0), "r"(a1), "r"(a2), "r"(a3), "r"(b0), "r"(b1));
}

__device__ __forceinline__ void cp_async16(uint32_t s, const void* g) {
    asm volatile("cp.async.ca.shared.global [%0], [%1], 16;" :: "r"(s), "l"(g));
}
__device__ __forceinline__ void cp_commit() {
    asm volatile("cp.async.commit_group;");
}
template<int N> __device__ __forceinline__ void cp_wait() {
    asm volatile("cp.async.wait_group %0;" :: "n"(N));
}

// ---------------------------------------------------------------------------
// elementwise tf32 pre-rounding (x and weights)
// ---------------------------------------------------------------------------
__global__ void round_copy(const float* __restrict__ src, float* __restrict__ dst, int n)
{
    int i = (blockIdx.x * blockDim.x + threadIdx.x) * 4;
    if (i < n) {
        float4 v = *(const float4*)(src + i);
        v.x = f2tff(v.x); v.y = f2tff(v.y); v.z = f2tff(v.z); v.w = f2tff(v.w);
        *(float4*)(dst + i) = v;
    }
}

// RoPE cos/sin table
__global__ void rope_table()
{
    int idx = blockIdx.x * blockDim.x + threadIdx.x; // SEQ*64
    int t = idx >> 6, j = idx & 63;
    float inv_freq = expf(-(float)j * (9.210340371976184f / 64.0f));
    float ang = (float)t * inv_freq;
    float sn, cs;
    sincosf(ang, &sn, &cs);
    g_tab[idx] = make_float2(cs, sn);
}

// ---------------------------------------------------------------------------
// warp-per-unit: units 0..15 = q heads (rmsnorm+rope+gain*scale+rna)
//                units 16..19 = k heads (rmsnorm+rope+rna)
//                units 20..23 = v heads (rna only)
// block = 256 threads = 8 units; grid = BT*24/8
// ---------------------------------------------------------------------------
__global__ __launch_bounds__(256) void norm_rope2(const float* __restrict__ q_gain)
{
    int u = blockIdx.x * 8 + (threadIdx.x >> 5);
    int lane = threadIdx.x & 31;
    int row = u / 24;
    int h = u - row * 24;

    if (h >= 20) { // v: round only
        float* p = g_v + (size_t)row * KVDIM + (h - 20) * HD;
        float4 v = make_float4(p[lane], p[lane + 32], p[lane + 64], p[lane + 96]);
        p[lane]      = f2tff(v.x);
        p[lane + 32] = f2tff(v.y);
        p[lane + 64] = f2tff(v.z);
        p[lane + 96] = f2tff(v.w);
        return;
    }

    float* p;
    float g;
    if (h < NHEADS) {
        p = g_q + (size_t)row * DIM + h * HD;
        g = q_gain[h] * 0.08838834764831845f; // fold 1/sqrt(128)
    } else {
        p = g_k + (size_t)row * KVDIM + (h - NHEADS) * HD;
        g = 1.0f;
    }

    float x1a = p[lane], x1b = p[lane + 32];
    float x2a = p[lane + 64], x2b = p[lane + 96];
    float ss = x1a * x1a + x1b * x1b + x2a * x2a + x2b * x2b;
#pragma unroll
    for (int o = 16; o; o >>= 1) ss += __shfl_xor_sync(0xffffffffu, ss, o);
    float r = rsqrtf(ss * (1.0f / 128.0f) + 1.1920928955078125e-07f);
    x1a *= r; x1b *= r; x2a *= r; x2b *= r;

    int t = row & (SEQ - 1);
    float2 csa = g_tab[t * 64 + lane];
    float2 csb = g_tab[t * 64 + lane + 32];

    p[lane]      = f2tff((x1a * csa.x + x2a * csa.y) * g);
    p[lane + 64] = f2tff((-x1a * csa.y + x2a * csa.x) * g);
    p[lane + 32] = f2tff((x1b * csb.x + x2b * csb.y) * g);
    p[lane + 96] = f2tff((-x1b * csb.y + x2b * csb.x) * g);
}

// ---------------------------------------------------------------------------
// tf32 tensor-core GEMM: C[M,N] = A[M,K] @ B[N,K]^T  (inputs pre-rounded tf32)
// BM=128, BN=128, BK=32, 256 threads (8 warps, 2x4), warp tile 64x32,
// cp.async double-buffered smem, per-thread 4x4 mma tiles.
// ---------------------------------------------------------------------------
#define SA 36  // smem row stride (floats): 36 % 32 == 4 -> conflict-free frags

__global__ __launch_bounds__(256, 2) void sgemm_tf32(const float* __restrict__ A,
                                                     const float* __restrict__ B,
                                                     float* __restrict__ C,
                                                     int M, int N, int K)
{
    extern __shared__ float sm[];
    float* As = sm;                 // [2][128*SA]
    float* Bs = sm + 2 * 128 * SA;  // [2][128*SA]

    const int tid = threadIdx.x;
    const int wid = tid >> 5, lane = tid & 31;
    const int wm = wid >> 2, wn = wid & 3;
    const int gid = lane >> 2, tig = lane & 3;
    const int row0 = blockIdx.y * 128, col0 = blockIdx.x * 128;

    const int lr = tid >> 3;   // 0..31 (row block per i)
    const int lc = tid & 7;    // float4 col

    uint32_t sAu = (uint32_t)__cvta_generic_to_shared(As);
    uint32_t sBu = (uint32_t)__cvta_generic_to_shared(Bs);

    float4 acc[4][4];
#pragma unroll
    for (int i = 0; i < 4; i++)
#pragma unroll
        for (int j = 0; j < 4; j++) acc[i][j] = make_float4(0.f, 0.f, 0.f, 0.f);

    auto load_tiles = [&](int k0, int buf) {
        uint32_t sa = sAu + buf * 128 * SA * 4;
        uint32_t sb = sBu + buf * 128 * SA * 4;
#pragma unroll
        for (int i = 0; i < 4; i++) {
            int r = i * 32 + lr;
            cp_async16(sa + (r * SA + lc * 4) * 4, A + (size_t)(row0 + r) * K + k0 + lc * 4);
            cp_async16(sb + (r * SA + lc * 4) * 4, B + (size_t)(col0 + r) * K + k0 + lc * 4);
        }
        cp_commit();
    };

    const int nIter = K >> 5;
    load_tiles(0, 0);

    for (int it = 0; it < nIter; it++) {
        int buf = it & 1;
        if (it + 1 < nIter) { load_tiles((it + 1) << 5, buf ^ 1); cp_wait<1>(); }
        else                { cp_wait<0>(); }
        __syncthreads();

        const float* as = As + buf * 128 * SA;
        const float* bs = Bs + buf * 128 * SA;
#pragma unroll
        for (int ks = 0; ks < 4; ks++) {
            uint32_t a[4][4], b[4][2];
#pragma unroll
            for (int mt = 0; mt < 4; mt++) {
                const float* p = as + (wm * 64 + mt * 16 + gid) * SA + ks * 8 + tig;
                a[mt][0] = __float_as_uint(p[0]);
                a[mt][1] = __float_as_uint(p[8 * SA]);
                a[mt][2] = __float_as_uint(p[4]);
                a[mt][3] = __float_as_uint(p[8 * SA + 4]);
            }
#pragma unroll
            for (int nt = 0; nt < 4; nt++) {
                const float* p = bs + (wn * 32 + nt * 8 + gid) * SA + ks * 8 + tig;
                b[nt][0] = __float_as_uint(p[0]);
                b[nt][1] = __float_as_uint(p[4]);
            }
#pragma unroll
            for (int mt = 0; mt < 4; mt++)
#pragma unroll
                for (int nt = 0; nt < 4; nt++)
                    mma_tf32(acc[mt][nt], a[mt][0], a[mt][1], a[mt][2], a[mt][3],
                             b[nt][0], b[nt][1]);
        }
        __syncthreads();
    }

#pragma unroll
    for (int mt = 0; mt < 4; mt++)
#pragma unroll
        for (int nt = 0; nt < 4; nt++) {
            int r = row0 + wm * 64 + mt * 16 + gid;
            int c = col0 + wn * 32 + nt * 8 + tig * 2;
            *(float2*)&C[(size_t)r * N + c]       = make_float2(acc[mt][nt].x, acc[mt][nt].y);
            *(float2*)&C[(size_t)(r + 8) * N + c] = make_float2(acc[mt][nt].z, acc[mt][nt].w);
        }
}

// ---------------------------------------------------------------------------
// Flash attention with tf32 mma. Block: 128 threads (4 warps), 64 q rows
// (16 per warp). Q fragments persistent in registers; K/V tiles via cp.async.
// ---------------------------------------------------------------------------
#define KSTR 132  // smem stride for K/V tiles (132 % 32 == 4)
#define PSTR 68   // smem stride for P

__global__ __launch_bounds__(128) void attn2()
{
    extern __shared__ float sm[];
    float* Ks = sm;                 // [64][KSTR]
    float* Vs = Ks + 64 * KSTR;     // [64][KSTR]
    float* Ps = Vs + 64 * KSTR;     // [64][PSTR]

    const int tid = threadIdx.x;
    const int wid = tid >> 5, lane = tid & 31;
    const int gid = lane >> 2, tig = lane & 3;
    const int qt = gridDim.x - 1 - blockIdx.x;   // big tiles first
    const int bh = blockIdx.y;
    const int b = bh >> 4, h = bh & 15, kvh = h >> 2;
    const int qb = qt * 64;

    uint32_t sKu = (uint32_t)__cvta_generic_to_shared(Ks);
    uint32_t sVu = (uint32_t)__cvta_generic_to_shared(Vs);

    // persistent Q fragments (pre-scaled + tf32-rounded by norm_rope2)
    uint32_t qf[16][4];
    {
        const float* Qg = g_q + ((size_t)(b * SEQ + qb + wid * 16 + gid)) * DIM + h * HD;
#pragma unroll
        for (int ks = 0; ks < 16; ks++) {
            const float* p = Qg + ks * 8 + tig;
            qf[ks][0] = __float_as_uint(p[0]);
            qf[ks][1] = __float_as_uint(p[8 * DIM]);
            qf[ks][2] = __float_as_uint(p[4]);
            qf[ks][3] = __float_as_uint(p[8 * DIM + 4]);
        }
    }

    float4 of[16];
#pragma unroll
    for (int i = 0; i < 16; i++) of[i] = make_float4(0.f, 0.f, 0.f, 0.f);
    float m0 = -FLT_MAX, m1 = -FLT_MAX, l0 = 0.f, l1 = 0.f;

    const int lr = tid >> 5;  // 0..3
    const int lc = lane;      // 0..31 (float4 col)

    for (int kt = 0; kt <= qt; kt++) {
        const int kbase = kt * 64;
        const float* Kg = g_k + ((size_t)(b * SEQ + kbase)) * KVDIM + kvh * HD;
        const float* Vg = g_v + ((size_t)(b * SEQ + kbase)) * KVDIM + kvh * HD;

#pragma unroll
        for (int i = 0; i < 16; i++) {
            int r = i * 4 + lr;
            cp_async16(sKu + (r * KSTR + lc * 4) * 4, Kg + (size_t)r * KVDIM + lc * 4);
            cp_async16(sVu + (r * KSTR + lc * 4) * 4, Vg + (size_t)r * KVDIM + lc * 4);
        }
        cp_commit();
        cp_wait<0>();
        __syncthreads();

        // S = Q K^T : 8 n-tiles x 16 k-steps
        float4 s[8];
#pragma unroll
        for (int nt = 0; nt < 8; nt++) s[nt] = make_float4(0.f, 0.f, 0.f, 0.f);
#pragma unroll
        for (int nt = 0; nt < 8; nt++) {
            const float* kp = Ks + (nt * 8 + gid) * KSTR + tig;
#pragma unroll
            for (int ks = 0; ks < 16; ks++) {
                uint32_t b0 = __float_as_uint(kp[ks * 8]);
                uint32_t b1 = __float_as_uint(kp[ks * 8 + 4]);
                mma_tf32(s[nt], qf[ks][0], qf[ks][1], qf[ks][2], qf[ks][3], b0, b1);
            }
        }

        // causal mask (only needed on diagonal tile)
        if (kt == qt) {
            int r0 = qb + wid * 16 + gid;
#pragma unroll
            for (int nt = 0; nt < 8; nt++) {
                int c = kbase + nt * 8 + 2 * tig;
                if (c > r0)         s[nt].x = -FLT_MAX;
                if (c + 1 > r0)     s[nt].y = -FLT_MAX;
                if (c > r0 + 8)     s[nt].z = -FLT_MAX;
                if (c + 1 > r0 + 8) s[nt].w = -FLT_MAX;
            }
        }

        // online softmax (rows gid and gid+8; 4 lanes per row share)
        float mt0 = -FLT_MAX, mt1 = -FLT_MAX;
#pragma unroll
        for (int nt = 0; nt < 8; nt++) {
            mt0 = fmaxf(mt0, fmaxf(s[nt].x, s[nt].y));
            mt1 = fmaxf(mt1, fmaxf(s[nt].z, s[nt].w));
        }
        mt0 = fmaxf(mt0, __shfl_xor_sync(0xffffffffu, mt0, 1));
        mt0 = fmaxf(mt0, __shfl_xor_sync(0xffffffffu, mt0, 2));
        mt1 = fmaxf(mt1, __shfl_xor_sync(0xffffffffu, mt1, 1));
        mt1 = fmaxf(mt1, __shfl_xor_sync(0xffffffffu, mt1, 2));

        float mn0 = fmaxf(m0, mt0), mn1 = fmaxf(m1, mt1);
        float a0 = __expf(m0 - mn0), a1 = __expf(m1 - mn1);
        float sum0 = 0.f, sum1 = 0.f;
#pragma unroll
        for (int nt = 0; nt < 8; nt++) {
            s[nt].x = __expf(s[nt].x - mn0);
            s[nt].y = __expf(s[nt].y - mn0);
            s[nt].z = __expf(s[nt].z - mn1);
            s[nt].w = __expf(s[nt].w - mn1);
            sum0 += s[nt].x + s[nt].y;
            sum1 += s[nt].z + s[nt].w;
        }
        sum0 += __shfl_xor_sync(0xffffffffu, sum0, 1);
        sum0 += __shfl_xor_sync(0xffffffffu, sum0, 2);
        sum1 += __shfl_xor_sync(0xffffffffu, sum1, 1);
        sum1 += __shfl_xor_sync(0xffffffffu, sum1, 2);

        l0 = l0 * a0 + sum0;
        l1 = l1 * a1 + sum1;
        m0 = mn0; m1 = mn1;
#pragma unroll
        for (int dt = 0; dt < 16; dt++) {
            of[dt].x *= a0; of[dt].y *= a0;
            of[dt].z *= a1; of[dt].w *= a1;
        }

        // stage P (tf32-rounded)
        {
            float* pr0 = Ps + (wid * 16 + gid) * PSTR + 2 * tig;
            float* pr1 = pr0 + 8 * PSTR;
#pragma unroll
            for (int nt = 0; nt < 8; nt++) {
                *(float2*)&pr0[nt * 8] = make_float2(f2tff(s[nt].x), f2tff(s[nt].y));
                *(float2*)&pr1[nt * 8] = make_float2(f2tff(s[nt].z), f2tff(s[nt].w));
            }
        }
        __syncwarp();

        // O += P V
        uint32_t pa[8][4];
#pragma unroll
        for (int ks = 0; ks < 8; ks++) {
            const float* p = Ps + (wid * 16 + gid) * PSTR + ks * 8 + tig;
            pa[ks][0] = __float_as_uint(p[0]);
            pa[ks][1] = __float_as_uint(p[8 * PSTR]);
            pa[ks][2] = __float_as_uint(p[4]);
            pa[ks][3] = __float_as_uint(p[8 * PSTR + 4]);
        }
#pragma unroll
        for (int dt = 0; dt < 16; dt++) {
            const float* vp = Vs + tig * KSTR + dt * 8 + gid;
#pragma unroll
            for (int ks = 0; ks < 8; ks++) {
                uint32_t b0 = __float_as_uint(vp[ks * 8 * KSTR]);
                uint32_t b1 = __float_as_uint(vp[(ks * 8 + 4) * KSTR]);
                mma_tf32(of[dt], pa[ks][0], pa[ks][1], pa[ks][2], pa[ks][3], b0, b1);
            }
        }
        __syncthreads();
    }

    // epilogue: normalize, tf32-round (feeds proj GEMM), store
    float inv0 = 1.0f / l0, inv1 = 1.0f / l1;
    float* Yg = g_y + ((size_t)(b * SEQ + qb + wid * 16 + gid)) * DIM + h * HD;
#pragma unroll
    for (int dt = 0; dt < 16; dt++) {
        int c = dt * 8 + 2 * tig;
        *(float2*)&Yg[c] = make_float2(f2tff(of[dt].x * inv0), f2tff(of[dt].y * inv0));
        *(float2*)&Yg[8 * DIM + c] = make_float2(f2tff(of[dt].z * inv1), f2tff(of[dt].w * inv1));
    }
}

// ---------------------------------------------------------------------------
extern "C" void kernel_launch(void* const* d_in, const int* in_sizes, int n_in,
                              void* d_out, int out_size)
{
    (void)in_sizes; (void)n_in; (void)out_size;
    const float* x  = (const float*)d_in[0];
    const float* qg = (const float*)d_in[1];
    const float* Wq = (const float*)d_in[2];
    const float* Wk = (const float*)d_in[3];
    const float* Wv = (const float*)d_in[4];
    const float* Wp = (const float*)d_in[5];
    float* out = (float*)d_out;

    float *qp, *kp, *vp, *yp, *xr, *wq, *wk, *wv, *wp;
    cudaGetSymbolAddress((void**)&qp, g_q);
    cudaGetSymbolAddress((void**)&kp, g_k);
    cudaGetSymbolAddress((void**)&vp, g_v);
    cudaGetSymbolAddress((void**)&yp, g_y);
    cudaGetSymbolAddress((void**)&xr, g_xr);
    cudaGetSymbolAddress((void**)&wq, g_wq);
    cudaGetSymbolAddress((void**)&wk, g_wk);
    cudaGetSymbolAddress((void**)&wv, g_wv);
    cudaGetSymbolAddress((void**)&wp, g_wp);

    // pre-round inputs to tf32
    round_copy<<<(BT * DIM) / 1024, 256>>>(x, xr, BT * DIM);
    round_copy<<<(DIM * DIM) / 1024, 256>>>(Wq, wq, DIM * DIM);
    round_copy<<<(KVDIM * DIM) / 1024, 256>>>(Wk, wk, KVDIM * DIM);
    round_copy<<<(KVDIM * DIM) / 1024, 256>>>(Wv, wv, KVDIM * DIM);
    round_copy<<<(DIM * DIM) / 1024, 256>>>(Wp, wp, DIM * DIM);
    rope_table<<<(SEQ * 64) / 256, 256>>>();

    size_t gsm = (size_t)(4 * 128 * SA) * sizeof(float);  // 73728
    cudaFuncSetAttribute(sgemm_tf32, cudaFuncAttributeMaxDynamicSharedMemorySize, (int)gsm);

    // QKV projections
    sgemm_tf32<<<dim3(DIM / 128, BT / 128), 256, gsm>>>(xr, wq, qp, BT, DIM, DIM);
    sgemm_tf32<<<dim3(KVDIM / 128, BT / 128), 256, gsm>>>(xr, wk, kp, BT, KVDIM, DIM);
    sgemm_tf32<<<dim3(KVDIM / 128, BT / 128), 256, gsm>>>(xr, wv, vp, BT, KVDIM, DIM);

    // norm + rope + gain + tf32 rounding (q, k, v)
    norm_rope2<<<(BT * 24) / 8, 256>>>(qg);

    // flash attention
    size_t asm_ = (size_t)(2 * 64 * KSTR + 64 * PSTR) * sizeof(float); // 84992
    cudaFuncSetAttribute(attn2, cudaFuncAttributeMaxDynamicSharedMemorySize, (int)asm_);
    attn2<<<dim3(SEQ / 64, BATCH * NHEADS), 128, asm_>>>();

    // output projection
    sgemm_tf32<<<dim3(DIM / 128, BT / 128), 256, gsm>>>(yp, wp, out, BT, DIM, DIM);
}

// round 4
// speedup vs baseline: 4.0966x; 1.0518x over previous
#include <cuda_runtime.h>
#include <math.h>
#include <float.h>
#include <stdint.h>

#define DIM 2048
#define QKVD 3072
#define NHEADS 16
#define NKV 4
#define HD 128
#define BATCH 2
#define SEQ 2048
#define BT (BATCH*SEQ)     // 4096
#define KVDIM 512

// Scratch (__device__ globals per allocation-free rule)
__device__ __align__(16) float g_qkv[(size_t)BT*QKVD];
__device__ __align__(16) float g_y[(size_t)BT*DIM];
__device__ __align__(16) float g_xr[(size_t)BT*DIM];
__device__ __align__(16) float g_wqkv[(size_t)QKVD*DIM];
__device__ __align__(16) float g_wp[(size_t)DIM*DIM];
__device__ __align__(16) float2 g_tab[SEQ*64];

// ---------------------------------------------------------------------------
// helpers
// ---------------------------------------------------------------------------
__device__ __forceinline__ uint32_t f2tf(float x) {
    uint32_t u;
    asm("cvt.rna.tf32.f32 %0, %1;" : "=r"(u) : "f"(x));
    return u;
}
__device__ __forceinline__ float f2tff(float x) { return __uint_as_float(f2tf(x)); }

__device__ __forceinline__ void mma_tf32(float4& c, uint32_t a0, uint32_t a1,
                                         uint32_t a2, uint32_t a3,
                                         uint32_t b0, uint32_t b1) {
    asm volatile(
        "mma.sync.aligned.m16n8k8.row.col.f32.tf32.tf32.f32 "
        "{%0,%1,%2,%3}, {%4,%5,%6,%7}, {%8,%9}, {%0,%1,%2,%3};"
        : "+f"(c.x), "+f"(c.y), "+f"(c.z), "+f"(c.w)
        : "r"(a0), "r"(a1), "r"(a2), "r"(a3), "r"(b0), "r"(b1));
}

__device__ __forceinline__ void cp_async16(uint32_t s, const void* g) {
    asm volatile("cp.async.ca.shared.global [%0], [%1], 16;" :: "r"(s), "l"(g));
}
__device__ __forceinline__ void cp_commit() {
    asm volatile("cp.async.commit_group;");
}
template<int N> __device__ __forceinline__ void cp_wait() {
    asm volatile("cp.async.wait_group %0;" :: "n"(N));
}

__device__ __forceinline__ uint32_t sm_u32(const void* p) {
    return (uint32_t)__cvta_generic_to_shared(p);
}

__device__ __forceinline__ void ldsm_x4(uint32_t* r, uint32_t addr) {
    asm volatile("ldmatrix.sync.aligned.m8n8.x4.shared.b16 {%0,%1,%2,%3}, [%4];"
                 : "=r"(r[0]), "=r"(r[1]), "=r"(r[2]), "=r"(r[3]) : "r"(addr));
}

// ---------------------------------------------------------------------------
// elementwise tf32 pre-rounding
// ---------------------------------------------------------------------------
__global__ void round_copy(const float* __restrict__ src, float* __restrict__ dst, int n)
{
    int i = (blockIdx.x * blockDim.x + threadIdx.x) * 4;
    if (i < n) {
        float4 v = *(const float4*)(src + i);
        v.x = f2tff(v.x); v.y = f2tff(v.y); v.z = f2tff(v.z); v.w = f2tff(v.w);
        *(float4*)(dst + i) = v;
    }
}

__global__ void rope_table()
{
    int idx = blockIdx.x * blockDim.x + threadIdx.x; // SEQ*64
    int t = idx >> 6, j = idx & 63;
    float inv_freq = expf(-(float)j * (9.210340371976184f / 64.0f));
    float ang = (float)t * inv_freq;
    float sn, cs;
    sincosf(ang, &sn, &cs);
    g_tab[idx] = make_float2(cs, sn);
}

// ---------------------------------------------------------------------------
// warp-per-unit norm/rope on fused qkv buffer
// units 0..15 q heads | 16..19 k heads | 20..23 v heads (round only)
// ---------------------------------------------------------------------------
__global__ __launch_bounds__(256) void norm_rope2(const float* __restrict__ q_gain)
{
    int u = blockIdx.x * 8 + (threadIdx.x >> 5);
    int lane = threadIdx.x & 31;
    int row = u / 24;
    int h = u - row * 24;

    if (h >= 20) {
        float* p = g_qkv + (size_t)row * QKVD + 2560 + (h - 20) * HD;
        float a = p[lane], b = p[lane + 32], c = p[lane + 64], d = p[lane + 96];
        p[lane]      = f2tff(a);
        p[lane + 32] = f2tff(b);
        p[lane + 64] = f2tff(c);
        p[lane + 96] = f2tff(d);
        return;
    }

    float* p;
    float g;
    if (h < NHEADS) {
        p = g_qkv + (size_t)row * QKVD + h * HD;
        g = q_gain[h] * 0.08838834764831845f; // fold 1/sqrt(128)
    } else {
        p = g_qkv + (size_t)row * QKVD + 2048 + (h - NHEADS) * HD;
        g = 1.0f;
    }

    float x1a = p[lane], x1b = p[lane + 32];
    float x2a = p[lane + 64], x2b = p[lane + 96];
    float ss = x1a * x1a + x1b * x1b + x2a * x2a + x2b * x2b;
#pragma unroll
    for (int o = 16; o; o >>= 1) ss += __shfl_xor_sync(0xffffffffu, ss, o);
    float r = rsqrtf(ss * (1.0f / 128.0f) + 1.1920928955078125e-07f);
    x1a *= r; x1b *= r; x2a *= r; x2b *= r;

    int t = row & (SEQ - 1);
    float2 csa = g_tab[t * 64 + lane];
    float2 csb = g_tab[t * 64 + lane + 32];

    p[lane]      = f2tff((x1a * csa.x + x2a * csa.y) * g);
    p[lane + 64] = f2tff((-x1a * csa.y + x2a * csa.x) * g);
    p[lane + 32] = f2tff((x1b * csb.x + x2b * csb.y) * g);
    p[lane + 96] = f2tff((-x1b * csb.y + x2b * csb.x) * g);
}

// ---------------------------------------------------------------------------
// HMMA tf32 GEMM: C[M,N] = A[M,K] @ B[N,K]^T, inputs pre-rounded tf32.
// CTA tile 128x128x32, 128 threads (4 warps in 2x2, warp tile 64x64).
// XOR-swizzled smem (32KB/stage), 3-stage cp.async pipeline, ldmatrix frags.
// ---------------------------------------------------------------------------
#define STAGE_B 32768

__global__ __launch_bounds__(128, 2) void gemm_hm(const float* __restrict__ A,
                                                  const float* __restrict__ B,
                                                  float* __restrict__ C,
                                                  int N, int K)
{
    extern __shared__ __align__(16) float smem[];
    const int tid = threadIdx.x;
    const int wid = tid >> 5, lane = tid & 31;
    const int wm = wid >> 1, wn = wid & 1;
    const int gid = lane >> 2, tig = lane & 3;
    const int row0 = blockIdx.y * 128, col0 = blockIdx.x * 128;
    uint32_t sbase = sm_u32(smem);

    float4 acc[4][8];
#pragma unroll
    for (int i = 0; i < 4; i++)
#pragma unroll
        for (int j = 0; j < 8; j++) acc[i][j] = make_float4(0.f, 0.f, 0.f, 0.f);

    auto ld_tile = [&](int t, int s) {
        int k0 = t << 5;
        uint32_t sa = sbase + s * STAGE_B;
        uint32_t sb = sa + 16384;
        const float* ga = A + (size_t)row0 * K + k0;
        const float* gb = B + (size_t)col0 * K + k0;
#pragma unroll
        for (int i = 0; i < 8; i++) {
            int chunk = tid + i * 128;         // 0..1023
            int r = chunk >> 3, c = chunk & 7; // row, 16B-chunk
            uint32_t off = (uint32_t)(r * 128 + ((c ^ (r & 7)) << 4));
            cp_async16(sa + off, ga + (size_t)r * K + c * 4);
            cp_async16(sb + off, gb + (size_t)r * K + c * 4);
        }
        cp_commit();
    };

    // ldmatrix lane-address components
    const int lx = lane & 7;
    const int l15 = lane & 15;
    const int lb16 = (lane >> 4) & 1;
    const int lb8 = (lane >> 3) & 1;

    const int nT = K >> 5;
    ld_tile(0, 0);
    ld_tile(1, 1);

    for (int t = 0; t < nT; t++) {
        if (t + 1 < nT) cp_wait<1>(); else cp_wait<0>();
        __syncthreads();
        if (t + 2 < nT) ld_tile(t + 2, (t + 2) % 3);

        uint32_t sa = sbase + (t % 3) * STAGE_B;
        uint32_t sb = sa + 16384;
#pragma unroll
        for (int ks = 0; ks < 4; ks++) {
            uint32_t a[4][4], b[4][4];
#pragma unroll
            for (int mt = 0; mt < 4; mt++) {
                uint32_t addr = sa + (uint32_t)((wm * 64 + mt * 16 + l15) * 128
                              + (((ks * 2 + lb16) ^ lx) << 4));
                ldsm_x4(a[mt], addr);
            }
#pragma unroll
            for (int p = 0; p < 4; p++) {
                uint32_t addr = sb + (uint32_t)((wn * 64 + p * 16 + lb16 * 8 + lx) * 128
                              + (((ks * 2 + lb8) ^ lx) << 4));
                ldsm_x4(b[p], addr);
            }
#pragma unroll
            for (int mt = 0; mt < 4; mt++)
#pragma unroll
                for (int p = 0; p < 4; p++) {
                    mma_tf32(acc[mt][2*p],     a[mt][0], a[mt][1], a[mt][2], a[mt][3],
                             b[p][0], b[p][1]);
                    mma_tf32(acc[mt][2*p + 1], a[mt][0], a[mt][1], a[mt][2], a[mt][3],
                             b[p][2], b[p][3]);
                }
        }
    }

#pragma unroll
    for (int mt = 0; mt < 4; mt++) {
        int r = row0 + wm * 64 + mt * 16 + gid;
#pragma unroll
        for (int nt = 0; nt < 8; nt++) {
            int c = col0 + wn * 64 + nt * 8 + tig * 2;
            *(float2*)&C[(size_t)r * N + c]       = make_float2(acc[mt][nt].x, acc[mt][nt].y);
            *(float2*)&C[(size_t)(r + 8) * N + c] = make_float2(acc[mt][nt].z, acc[mt][nt].w);
        }
    }
}

// ---------------------------------------------------------------------------
// Flash attention with mma.sync tf32 (identical to passing R2 version)
// ---------------------------------------------------------------------------
#define KSTR 132
#define PSTR 68

__global__ __launch_bounds__(128) void attn2()
{
    extern __shared__ float sm[];
    float* Ks = sm;
    float* Vs = Ks + 64 * KSTR;
    float* Ps = Vs + 64 * KSTR;

    const int tid = threadIdx.x;
    const int wid = tid >> 5, lane = tid & 31;
    const int gid = lane >> 2, tig = lane & 3;
    const int qt = gridDim.x - 1 - blockIdx.x;
    const int bh = blockIdx.y;
    const int b = bh >> 4, h = bh & 15, kvh = h >> 2;
    const int qb = qt * 64;

    uint32_t sKu = sm_u32(Ks);
    uint32_t sVu = sm_u32(Vs);

    uint32_t qf[16][4];
    {
        const float* Qg = g_qkv + ((size_t)(b * SEQ + qb + wid * 16 + gid)) * QKVD + h * HD;
#pragma unroll
        for (int ks = 0; ks < 16; ks++) {
            const float* p = Qg + ks * 8 + tig;
            qf[ks][0] = __float_as_uint(p[0]);
            qf[ks][1] = __float_as_uint(p[8 * QKVD]);
            qf[ks][2] = __float_as_uint(p[4]);
            qf[ks][3] = __float_as_uint(p[8 * QKVD + 4]);
        }
    }

    float4 of[16];
#pragma unroll
    for (int i = 0; i < 16; i++) of[i] = make_float4(0.f, 0.f, 0.f, 0.f);
    float m0 = -FLT_MAX, m1 = -FLT_MAX, l0 = 0.f, l1 = 0.f;

    const int lr = tid >> 5;
    const int lc = lane;

    for (int kt = 0; kt <= qt; kt++) {
        const int kbase = kt * 64;
        const float* Kg = g_qkv + ((size_t)(b * SEQ + kbase)) * QKVD + 2048 + kvh * HD;
        const float* Vg = g_qkv + ((size_t)(b * SEQ + kbase)) * QKVD + 2560 + kvh * HD;

#pragma unroll
        for (int i = 0; i < 16; i++) {
            int r = i * 4 + lr;
            cp_async16(sKu + (r * KSTR + lc * 4) * 4, Kg + (size_t)r * QKVD + lc * 4);
            cp_async16(sVu + (r * KSTR + lc * 4) * 4, Vg + (size_t)r * QKVD + lc * 4);
        }
        cp_commit();
        cp_wait<0>();
        __syncthreads();

        float4 s[8];
#pragma unroll
        for (int nt = 0; nt < 8; nt++) s[nt] = make_float4(0.f, 0.f, 0.f, 0.f);
#pragma unroll
        for (int nt = 0; nt < 8; nt++) {
            const float* kp = Ks + (nt * 8 + gid) * KSTR + tig;
#pragma unroll
            for (int ks = 0; ks < 16; ks++) {
                uint32_t b0 = __float_as_uint(kp[ks * 8]);
                uint32_t b1 = __float_as_uint(kp[ks * 8 + 4]);
                mma_tf32(s[nt], qf[ks][0], qf[ks][1], qf[ks][2], qf[ks][3], b0, b1);
            }
        }

        if (kt == qt) {
            int r0 = qb + wid * 16 + gid;
#pragma unroll
            for (int nt = 0; nt < 8; nt++) {
                int c = kbase + nt * 8 + 2 * tig;
                if (c > r0)         s[nt].x = -FLT_MAX;
                if (c + 1 > r0)     s[nt].y = -FLT_MAX;
                if (c > r0 + 8)     s[nt].z = -FLT_MAX;
                if (c + 1 > r0 + 8) s[nt].w = -FLT_MAX;
            }
        }

        float mt0 = -FLT_MAX, mt1 = -FLT_MAX;
#pragma unroll
        for (int nt = 0; nt < 8; nt++) {
            mt0 = fmaxf(mt0, fmaxf(s[nt].x, s[nt].y));
            mt1 = fmaxf(mt1, fmaxf(s[nt].z, s[nt].w));
        }
        mt0 = fmaxf(mt0, __shfl_xor_sync(0xffffffffu, mt0, 1));
        mt0 = fmaxf(mt0, __shfl_xor_sync(0xffffffffu, mt0, 2));
        mt1 = fmaxf(mt1, __shfl_xor_sync(0xffffffffu, mt1, 1));
        mt1 = fmaxf(mt1, __shfl_xor_sync(0xffffffffu, mt1, 2));

        float mn0 = fmaxf(m0, mt0), mn1 = fmaxf(m1, mt1);
        float a0 = __expf(m0 - mn0), a1 = __expf(m1 - mn1);
        float sum0 = 0.f, sum1 = 0.f;
#pragma unroll
        for (int nt = 0; nt < 8; nt++) {
            s[nt].x = __expf(s[nt].x - mn0);
            s[nt].y = __expf(s[nt].y - mn0);
            s[nt].z = __expf(s[nt].z - mn1);
            s[nt].w = __expf(s[nt].w - mn1);
            sum0 += s[nt].x + s[nt].y;
            sum1 += s[nt].z + s[nt].w;
        }
        sum0 += __shfl_xor_sync(0xffffffffu, sum0, 1);
        sum0 += __shfl_xor_sync(0xffffffffu, sum0, 2);
        sum1 += __shfl_xor_sync(0xffffffffu, sum1, 1);
        sum1 += __shfl_xor_sync(0xffffffffu, sum1, 2);

        l0 = l0 * a0 + sum0;
        l1 = l1 * a1 + sum1;
        m0 = mn0; m1 = mn1;
#pragma unroll
        for (int dt = 0; dt < 16; dt++) {
            of[dt].x *= a0; of[dt].y *= a0;
            of[dt].z *= a1; of[dt].w *= a1;
        }

        {
            float* pr0 = Ps + (wid * 16 + gid) * PSTR + 2 * tig;
            float* pr1 = pr0 + 8 * PSTR;
#pragma unroll
            for (int nt = 0; nt < 8; nt++) {
                *(float2*)&pr0[nt * 8] = make_float2(f2tff(s[nt].x), f2tff(s[nt].y));
                *(float2*)&pr1[nt * 8] = make_float2(f2tff(s[nt].z), f2tff(s[nt].w));
            }
        }
        __syncwarp();

        uint32_t pa[8][4];
#pragma unroll
        for (int ks = 0; ks < 8; ks++) {
            const float* p = Ps + (wid * 16 + gid) * PSTR + ks * 8 + tig;
            pa[ks][0] = __float_as_uint(p[0]);
            pa[ks][1] = __float_as_uint(p[8 * PSTR]);
            pa[ks][2] = __float_as_uint(p[4]);
            pa[ks][3] = __float_as_uint(p[8 * PSTR + 4]);
        }
#pragma unroll
        for (int dt = 0; dt < 16; dt++) {
            const float* vp = Vs + tig * KSTR + dt * 8 + gid;
#pragma unroll
            for (int ks = 0; ks < 8; ks++) {
                uint32_t b0 = __float_as_uint(vp[ks * 8 * KSTR]);
                uint32_t b1 = __float_as_uint(vp[(ks * 8 + 4) * KSTR]);
                mma_tf32(of[dt], pa[ks][0], pa[ks][1], pa[ks][2], pa[ks][3], b0, b1);
            }
        }
        __syncthreads();
    }

    float inv0 = 1.0f / l0, inv1 = 1.0f / l1;
    float* Yg = g_y + ((size_t)(b * SEQ + qb + wid * 16 + gid)) * DIM + h * HD;
#pragma unroll
    for (int dt = 0; dt < 16; dt++) {
        int c = dt * 8 + 2 * tig;
        *(float2*)&Yg[c] = make_float2(f2tff(of[dt].x * inv0), f2tff(of[dt].y * inv0));
        *(float2*)&Yg[8 * DIM + c] = make_float2(f2tff(of[dt].z * inv1), f2tff(of[dt].w * inv1));
    }
}

// ---------------------------------------------------------------------------
extern "C" void kernel_launch(void* const* d_in, const int* in_sizes, int n_in,
                              void* d_out, int out_size)
{
    (void)in_sizes; (void)n_in; (void)out_size;
    const float* x  = (const float*)d_in[0];
    const float* qg = (const float*)d_in[1];
    const float* Wq = (const float*)d_in[2];
    const float* Wk = (const float*)d_in[3];
    const float* Wv = (const float*)d_in[4];
    const float* Wp = (const float*)d_in[5];
    float* out = (float*)d_out;

    float *qkv, *yp, *xr, *wqkv, *wp;
    cudaGetSymbolAddress((void**)&qkv, g_qkv);
    cudaGetSymbolAddress((void**)&yp, g_y);
    cudaGetSymbolAddress((void**)&xr, g_xr);
    cudaGetSymbolAddress((void**)&wqkv, g_wqkv);
    cudaGetSymbolAddress((void**)&wp, g_wp);

    // tf32 pre-rounding; W_q/W_k/W_v fused into one [3072, 2048] weight
    round_copy<<<(BT * DIM) / 1024, 256>>>(x, xr, BT * DIM);
    round_copy<<<(DIM * DIM) / 1024, 256>>>(Wq, wqkv, DIM * DIM);
    round_copy<<<(KVDIM * DIM) / 1024, 256>>>(Wk, wqkv + (size_t)2048 * DIM, KVDIM * DIM);
    round_copy<<<(KVDIM * DIM) / 1024, 256>>>(Wv, wqkv + (size_t)2560 * DIM, KVDIM * DIM);
    round_copy<<<(DIM * DIM) / 1024, 256>>>(Wp, wp, DIM * DIM);
    rope_table<<<(SEQ * 64) / 256, 256>>>();

    size_t gsm = 3 * (size_t)STAGE_B;  // 98304
    cudaFuncSetAttribute(gemm_hm, cudaFuncAttributeMaxDynamicSharedMemorySize, (int)gsm);

    // fused QKV projection: [4096, 3072] = xr @ wqkv^T
    gemm_hm<<<dim3(QKVD / 128, BT / 128), 128, gsm>>>(xr, wqkv, qkv, QKVD, DIM);

    // norm + rope + gain + tf32 rounding
    norm_rope2<<<(BT * 24) / 8, 256>>>(qg);

    // flash attention
    size_t asm_ = (size_t)(2 * 64 * KSTR + 64 * PSTR) * sizeof(float);
    cudaFuncSetAttribute(attn2, cudaFuncAttributeMaxDynamicSharedMemorySize, (int)asm_);
    attn2<<<dim3(SEQ / 64, BATCH * NHEADS), 128, asm_>>>();

    // output projection
    gemm_hm<<<dim3(DIM / 128, BT / 128), 128, gsm>>>(yp, wp, out, DIM, DIM);
}

// round 5
// speedup vs baseline: 4.2178x; 1.0296x over previous
#include <cuda_runtime.h>
#include <math.h>
#include <float.h>
#include <stdint.h>

#define DIM 2048
#define QKVD 3072
#define NHEADS 16
#define NKV 4
#define HD 128
#define BATCH 2
#define SEQ 2048
#define BT (BATCH*SEQ)     // 4096
#define KVDIM 512

// Scratch (__device__ globals per allocation-free rule)
__device__ __align__(16) float g_qkv[(size_t)BT*QKVD];
__device__ __align__(16) float g_y[(size_t)BT*DIM];
__device__ __align__(16) float g_xr[(size_t)BT*DIM];
__device__ __align__(16) float g_wqkv[(size_t)QKVD*DIM];
__device__ __align__(16) float g_wp[(size_t)DIM*DIM];
__device__ __align__(16) float2 g_tab[SEQ*64];

// ---------------------------------------------------------------------------
// helpers
// ---------------------------------------------------------------------------
__device__ __forceinline__ uint32_t f2tf(float x) {
    uint32_t u;
    asm("cvt.rna.tf32.f32 %0, %1;" : "=r"(u) : "f"(x));
    return u;
}
__device__ __forceinline__ float f2tff(float x) { return __uint_as_float(f2tf(x)); }

__device__ __forceinline__ void mma_tf32(float4& c, uint32_t a0, uint32_t a1,
                                         uint32_t a2, uint32_t a3,
                                         uint32_t b0, uint32_t b1) {
    asm volatile(
        "mma.sync.aligned.m16n8k8.row.col.f32.tf32.tf32.f32 "
        "{%0,%1,%2,%3}, {%4,%5,%6,%7}, {%8,%9}, {%0,%1,%2,%3};"
        : "+f"(c.x), "+f"(c.y), "+f"(c.z), "+f"(c.w)
        : "r"(a0), "r"(a1), "r"(a2), "r"(a3), "r"(b0), "r"(b1));
}

__device__ __forceinline__ void cp_async16(uint32_t s, const void* g) {
    asm volatile("cp.async.ca.shared.global [%0], [%1], 16;" :: "r"(s), "l"(g));
}
__device__ __forceinline__ void cp_commit() {
    asm volatile("cp.async.commit_group;");
}
template<int N> __device__ __forceinline__ void cp_wait() {
    asm volatile("cp.async.wait_group %0;" :: "n"(N));
}

__device__ __forceinline__ uint32_t sm_u32(const void* p) {
    return (uint32_t)__cvta_generic_to_shared(p);
}

__device__ __forceinline__ void ldsm_x4(uint32_t* r, uint32_t addr) {
    asm volatile("ldmatrix.sync.aligned.m8n8.x4.shared.b16 {%0,%1,%2,%3}, [%4];"
                 : "=r"(r[0]), "=r"(r[1]), "=r"(r[2]), "=r"(r[3]) : "r"(addr));
}

// ---------------------------------------------------------------------------
// prep_all: tf32 pre-rounding of x + 4 weight tensors, plus RoPE table.
// One launch (keeps attn2 at launch slot 4 for ncu).
// Segments in float4 units: x 2M | wq 1M | wk 256K | wv 256K | wp 1M | tab.
// ---------------------------------------------------------------------------
#define BL_X  8192
#define BL_WQ 4096
#define BL_WK 1024
#define BL_WV 1024
#define BL_WP 4096
#define BL_TB 512

__global__ __launch_bounds__(256) void prep_all(const float* __restrict__ x,
                                                const float* __restrict__ Wq,
                                                const float* __restrict__ Wk,
                                                const float* __restrict__ Wv,
                                                const float* __restrict__ Wp)
{
    int blk = blockIdx.x;
    const float* src;
    float* dst;
    if (blk < BL_X)        { src = x;  dst = g_xr; }
    else if ((blk -= BL_X) < BL_WQ)  { src = Wq; dst = g_wqkv; }
    else if ((blk -= BL_WQ) < BL_WK) { src = Wk; dst = g_wqkv + (size_t)2048 * DIM; }
    else if ((blk -= BL_WK) < BL_WV) { src = Wv; dst = g_wqkv + (size_t)2560 * DIM; }
    else if ((blk -= BL_WV) < BL_WP) { src = Wp; dst = g_wp; }
    else {
        blk -= BL_WP;   // rope table: 512 blocks x 256 threads = SEQ*64
        int idx = blk * 256 + threadIdx.x;
        int t = idx >> 6, j = idx & 63;
        float inv_freq = expf(-(float)j * (9.210340371976184f / 64.0f));
        float ang = (float)t * inv_freq;
        float sn, cs;
        sincosf(ang, &sn, &cs);
        g_tab[idx] = make_float2(cs, sn);
        return;
    }
    int i = (blk * 256 + threadIdx.x) * 4;
    float4 v = *(const float4*)(src + i);
    v.x = f2tff(v.x); v.y = f2tff(v.y); v.z = f2tff(v.z); v.w = f2tff(v.w);
    *(float4*)(dst + i) = v;
}

// ---------------------------------------------------------------------------
// warp-per-unit norm/rope on fused qkv buffer
// ---------------------------------------------------------------------------
__global__ __launch_bounds__(256) void norm_rope2(const float* __restrict__ q_gain)
{
    int u = blockIdx.x * 8 + (threadIdx.x >> 5);
    int lane = threadIdx.x & 31;
    int row = u / 24;
    int h = u - row * 24;

    if (h >= 20) {
        float* p = g_qkv + (size_t)row * QKVD + 2560 + (h - 20) * HD;
        float a = p[lane], b = p[lane + 32], c = p[lane + 64], d = p[lane + 96];
        p[lane]      = f2tff(a);
        p[lane + 32] = f2tff(b);
        p[lane + 64] = f2tff(c);
        p[lane + 96] = f2tff(d);
        return;
    }

    float* p;
    float g;
    if (h < NHEADS) {
        p = g_qkv + (size_t)row * QKVD + h * HD;
        g = q_gain[h] * 0.08838834764831845f;
    } else {
        p = g_qkv + (size_t)row * QKVD + 2048 + (h - NHEADS) * HD;
        g = 1.0f;
    }

    float x1a = p[lane], x1b = p[lane + 32];
    float x2a = p[lane + 64], x2b = p[lane + 96];
    float ss = x1a * x1a + x1b * x1b + x2a * x2a + x2b * x2b;
#pragma unroll
    for (int o = 16; o; o >>= 1) ss += __shfl_xor_sync(0xffffffffu, ss, o);
    float r = rsqrtf(ss * (1.0f / 128.0f) + 1.1920928955078125e-07f);
    x1a *= r; x1b *= r; x2a *= r; x2b *= r;

    int t = row & (SEQ - 1);
    float2 csa = g_tab[t * 64 + lane];
    float2 csb = g_tab[t * 64 + lane + 32];

    p[lane]      = f2tff((x1a * csa.x + x2a * csa.y) * g);
    p[lane + 64] = f2tff((-x1a * csa.y + x2a * csa.x) * g);
    p[lane + 32] = f2tff((x1b * csb.x + x2b * csb.y) * g);
    p[lane + 96] = f2tff((-x1b * csb.y + x2b * csb.x) * g);
}

// ---------------------------------------------------------------------------
// HMMA tf32 GEMM (unchanged from R4)
// ---------------------------------------------------------------------------
#define STAGE_B 32768

__global__ __launch_bounds__(128, 2) void gemm_hm(const float* __restrict__ A,
                                                  const float* __restrict__ B,
                                                  float* __restrict__ C,
                                                  int N, int K)
{
    extern __shared__ __align__(16) float smem[];
    const int tid = threadIdx.x;
    const int wid = tid >> 5, lane = tid & 31;
    const int wm = wid >> 1, wn = wid & 1;
    const int gid = lane >> 2, tig = lane & 3;
    const int row0 = blockIdx.y * 128, col0 = blockIdx.x * 128;
    uint32_t sbase = sm_u32(smem);

    float4 acc[4][8];
#pragma unroll
    for (int i = 0; i < 4; i++)
#pragma unroll
        for (int j = 0; j < 8; j++) acc[i][j] = make_float4(0.f, 0.f, 0.f, 0.f);

    auto ld_tile = [&](int t, int s) {
        int k0 = t << 5;
        uint32_t sa = sbase + s * STAGE_B;
        uint32_t sb = sa + 16384;
        const float* ga = A + (size_t)row0 * K + k0;
        const float* gb = B + (size_t)col0 * K + k0;
#pragma unroll
        for (int i = 0; i < 8; i++) {
            int chunk = tid + i * 128;
            int r = chunk >> 3, c = chunk & 7;
            uint32_t off = (uint32_t)(r * 128 + ((c ^ (r & 7)) << 4));
            cp_async16(sa + off, ga + (size_t)r * K + c * 4);
            cp_async16(sb + off, gb + (size_t)r * K + c * 4);
        }
        cp_commit();
    };

    const int lx = lane & 7;
    const int l15 = lane & 15;
    const int lb16 = (lane >> 4) & 1;
    const int lb8 = (lane >> 3) & 1;

    const int nT = K >> 5;
    ld_tile(0, 0);
    ld_tile(1, 1);

    for (int t = 0; t < nT; t++) {
        if (t + 1 < nT) cp_wait<1>(); else cp_wait<0>();
        __syncthreads();
        if (t + 2 < nT) ld_tile(t + 2, (t + 2) % 3);

        uint32_t sa = sbase + (t % 3) * STAGE_B;
        uint32_t sb = sa + 16384;
#pragma unroll
        for (int ks = 0; ks < 4; ks++) {
            uint32_t a[4][4], b[4][4];
#pragma unroll
            for (int mt = 0; mt < 4; mt++) {
                uint32_t addr = sa + (uint32_t)((wm * 64 + mt * 16 + l15) * 128
                              + (((ks * 2 + lb16) ^ lx) << 4));
                ldsm_x4(a[mt], addr);
            }
#pragma unroll
            for (int p = 0; p < 4; p++) {
                uint32_t addr = sb + (uint32_t)((wn * 64 + p * 16 + lb16 * 8 + lx) * 128
                              + (((ks * 2 + lb8) ^ lx) << 4));
                ldsm_x4(b[p], addr);
            }
#pragma unroll
            for (int mt = 0; mt < 4; mt++)
#pragma unroll
                for (int p = 0; p < 4; p++) {
                    mma_tf32(acc[mt][2*p],     a[mt][0], a[mt][1], a[mt][2], a[mt][3],
                             b[p][0], b[p][1]);
                    mma_tf32(acc[mt][2*p + 1], a[mt][0], a[mt][1], a[mt][2], a[mt][3],
                             b[p][2], b[p][3]);
                }
        }
    }

#pragma unroll
    for (int mt = 0; mt < 4; mt++) {
        int r = row0 + wm * 64 + mt * 16 + gid;
#pragma unroll
        for (int nt = 0; nt < 8; nt++) {
            int c = col0 + wn * 64 + nt * 8 + tig * 2;
            *(float2*)&C[(size_t)r * N + c]       = make_float2(acc[mt][nt].x, acc[mt][nt].y);
            *(float2*)&C[(size_t)(r + 8) * N + c] = make_float2(acc[mt][nt].z, acc[mt][nt].w);
        }
    }
}

// ---------------------------------------------------------------------------
// Flash attention, pipelined: phase-shifted K/V cp.async prefetch,
// ldmatrix fragments for K and P, scalar LDS for V.
// smem: Ks 64x512B swizzled (32KB) | Vs 64x132 f32 | Ps 64x68 f32 -> ~84KB.
// ---------------------------------------------------------------------------
#define KSTR 132
#define PSTR 68

__global__ __launch_bounds__(128) void attn2()
{
    extern __shared__ __align__(16) float sm[];
    float* Ks = sm;                       // [64][128] swizzled, 512B rows
    float* Vs = Ks + 64 * 128;            // [64][KSTR]
    float* Ps = Vs + 64 * KSTR;           // [64][PSTR]

    const int tid = threadIdx.x;
    const int wid = tid >> 5, lane = tid & 31;
    const int gid = lane >> 2, tig = lane & 3;
    const int qt = gridDim.x - 1 - blockIdx.x;
    const int bh = blockIdx.y;
    const int b = bh >> 4, h = bh & 15, kvh = h >> 2;
    const int qb = qt * 64;

    uint32_t sKu = sm_u32(Ks);
    uint32_t sVu = sm_u32(Vs);
    uint32_t sPu = sm_u32(Ps);

    const float* Kg0 = g_qkv + (size_t)(b * SEQ) * QKVD + 2048 + kvh * HD;
    const float* Vg0 = Kg0 + 512;

    // persistent Q fragments (pre-scaled + tf32-rounded by norm_rope2)
    uint32_t qf[16][4];
    {
        const float* Qg = g_qkv + ((size_t)(b * SEQ + qb + wid * 16 + gid)) * QKVD + h * HD;
#pragma unroll
        for (int ks = 0; ks < 16; ks++) {
            const float* p = Qg + ks * 8 + tig;
            qf[ks][0] = __float_as_uint(p[0]);
            qf[ks][1] = __float_as_uint(p[8 * QKVD]);
            qf[ks][2] = __float_as_uint(p[4]);
            qf[ks][3] = __float_as_uint(p[8 * QKVD + 4]);
        }
    }

    // cp.async loaders: K -> swizzled 512B rows; V -> KSTR row-major
    auto ld_K = [&](int kt) {
        const float* Kg = Kg0 + (size_t)(kt * 64) * QKVD;
#pragma unroll
        for (int i = 0; i < 16; i++) {
            int id = tid + i * 128;           // 0..2047
            int r = id >> 5, c = id & 31;
            uint32_t off = (uint32_t)(r * 512 + ((c ^ (r & 7)) << 4));
            cp_async16(sKu + off, Kg + (size_t)r * QKVD + c * 4);
        }
        cp_commit();
    };
    auto ld_V = [&](int kt) {
        const float* Vg = Vg0 + (size_t)(kt * 64) * QKVD;
#pragma unroll
        for (int i = 0; i < 16; i++) {
            int id = tid + i * 128;
            int r = id >> 5, c = id & 31;
            cp_async16(sVu + (uint32_t)(r * KSTR + c * 4) * 4,
                       Vg + (size_t)r * QKVD + c * 4);
        }
        cp_commit();
    };

    float4 of[16];
#pragma unroll
    for (int i = 0; i < 16; i++) of[i] = make_float4(0.f, 0.f, 0.f, 0.f);
    float m0 = -FLT_MAX, m1 = -FLT_MAX, l0 = 0.f, l1 = 0.f;

    // ldsm lane addressing (K): tiles = [rows p*16.. | +8] x [chunk 2ks | +1]
    const int krow = ((lane >> 4) & 1) * 8 + (lane & 7);
    const int kcb  = (lane >> 3) & 1;
    // ldsm lane addressing (P): tiles = [rows wid*16.. | +8] x [chunk 2ks | +1]
    const int prow = wid * 16 + ((lane >> 3) & 1) * 8 + (lane & 7);
    const int pcb  = (lane >> 4) & 1;
    const uint32_t pbase = sPu + (uint32_t)(prow * PSTR * 4 + pcb * 16);

    ld_K(0);
    ld_V(0);

    for (int kt = 0; kt <= qt; kt++) {
        const int kbase = kt * 64;
        const int ktn = (kt + 1 <= qt) ? kt + 1 : qt;

        cp_wait<1>();          // K[kt] arrived (V[kt] still pending)
        __syncthreads();

        // S = Q K^T via ldsm K fragments
        float4 s[8];
#pragma unroll
        for (int nt = 0; nt < 8; nt++) s[nt] = make_float4(0.f, 0.f, 0.f, 0.f);
#pragma unroll
        for (int p = 0; p < 4; p++) {
            const int row = p * 16 + krow;
            const uint32_t rowaddr = sKu + (uint32_t)(row * 512);
            const int rx = row & 7;
#pragma unroll
            for (int ks = 0; ks < 16; ks++) {
                uint32_t kb[4];
                ldsm_x4(kb, rowaddr + (uint32_t)(((2 * ks + kcb) ^ rx) << 4));
                mma_tf32(s[2*p],     qf[ks][0], qf[ks][1], qf[ks][2], qf[ks][3],
                         kb[0], kb[1]);
                mma_tf32(s[2*p + 1], qf[ks][0], qf[ks][1], qf[ks][2], qf[ks][3],
                         kb[2], kb[3]);
            }
        }
        __syncthreads();       // all warps done reading Ks
        ld_K(ktn);             // prefetch next K (overlaps softmax + PV)

        // causal mask on diagonal tile
        if (kt == qt) {
            int r0 = qb + wid * 16 + gid;
#pragma unroll
            for (int nt = 0; nt < 8; nt++) {
                int c = kbase + nt * 8 + 2 * tig;
                if (c > r0)         s[nt].x = -FLT_MAX;
                if (c + 1 > r0)     s[nt].y = -FLT_MAX;
                if (c > r0 + 8)     s[nt].z = -FLT_MAX;
                if (c + 1 > r0 + 8) s[nt].w = -FLT_MAX;
            }
        }

        // online softmax
        float mt0 = -FLT_MAX, mt1 = -FLT_MAX;
#pragma unroll
        for (int nt = 0; nt < 8; nt++) {
            mt0 = fmaxf(mt0, fmaxf(s[nt].x, s[nt].y));
            mt1 = fmaxf(mt1, fmaxf(s[nt].z, s[nt].w));
        }
        mt0 = fmaxf(mt0, __shfl_xor_sync(0xffffffffu, mt0, 1));
        mt0 = fmaxf(mt0, __shfl_xor_sync(0xffffffffu, mt0, 2));
        mt1 = fmaxf(mt1, __shfl_xor_sync(0xffffffffu, mt1, 1));
        mt1 = fmaxf(mt1, __shfl_xor_sync(0xffffffffu, mt1, 2));

        float mn0 = fmaxf(m0, mt0), mn1 = fmaxf(m1, mt1);
        float a0 = __expf(m0 - mn0), a1 = __expf(m1 - mn1);
        float sum0 = 0.f, sum1 = 0.f;
#pragma unroll
        for (int nt = 0; nt < 8; nt++) {
            s[nt].x = __expf(s[nt].x - mn0);
            s[nt].y = __expf(s[nt].y - mn0);
            s[nt].z = __expf(s[nt].z - mn1);
            s[nt].w = __expf(s[nt].w - mn1);
            sum0 += s[nt].x + s[nt].y;
            sum1 += s[nt].z + s[nt].w;
        }
        sum0 += __shfl_xor_sync(0xffffffffu, sum0, 1);
        sum0 += __shfl_xor_sync(0xffffffffu, sum0, 2);
        sum1 += __shfl_xor_sync(0xffffffffu, sum1, 1);
        sum1 += __shfl_xor_sync(0xffffffffu, sum1, 2);

        l0 = l0 * a0 + sum0;
        l1 = l1 * a1 + sum1;
        m0 = mn0; m1 = mn1;
#pragma unroll
        for (int dt = 0; dt < 16; dt++) {
            of[dt].x *= a0; of[dt].y *= a0;
            of[dt].z *= a1; of[dt].w *= a1;
        }

        // stage P (tf32-rounded) to smem, warp-private rows
        {
            float* pr0 = Ps + (wid * 16 + gid) * PSTR + 2 * tig;
            float* pr1 = pr0 + 8 * PSTR;
#pragma unroll
            for (int nt = 0; nt < 8; nt++) {
                *(float2*)&pr0[nt * 8] = make_float2(f2tff(s[nt].x), f2tff(s[nt].y));
                *(float2*)&pr1[nt * 8] = make_float2(f2tff(s[nt].z), f2tff(s[nt].w));
            }
        }
        __syncwarp();

        cp_wait<1>();          // V[kt] arrived (next K pending)
        __syncthreads();

        // P fragments via ldsm
        uint32_t pa[8][4];
#pragma unroll
        for (int ks = 0; ks < 8; ks++)
            ldsm_x4(pa[ks], pbase + (uint32_t)(ks * 32));

        // O += P V  (V scalar loads, conflict-free)
#pragma unroll
        for (int dt = 0; dt < 16; dt++) {
            const float* vp = Vs + tig * KSTR + dt * 8 + gid;
#pragma unroll
            for (int ks = 0; ks < 8; ks++) {
                uint32_t b0 = __float_as_uint(vp[ks * 8 * KSTR]);
                uint32_t b1 = __float_as_uint(vp[(ks * 8 + 4) * KSTR]);
                mma_tf32(of[dt], pa[ks][0], pa[ks][1], pa[ks][2], pa[ks][3], b0, b1);
            }
        }
        __syncthreads();       // all warps done reading Vs
        ld_V(ktn);             // prefetch next V (overlaps next S phase)
    }
    cp_wait<0>();              // drain trailing prefetches

    float inv0 = 1.0f / l0, inv1 = 1.0f / l1;
    float* Yg = g_y + ((size_t)(b * SEQ + qb + wid * 16 + gid)) * DIM + h * HD;
#pragma unroll
    for (int dt = 0; dt < 16; dt++) {
        int c = dt * 8 + 2 * tig;
        *(float2*)&Yg[c] = make_float2(f2tff(of[dt].x * inv0), f2tff(of[dt].y * inv0));
        *(float2*)&Yg[8 * DIM + c] = make_float2(f2tff(of[dt].z * inv1), f2tff(of[dt].w * inv1));
    }
}

// ---------------------------------------------------------------------------
extern "C" void kernel_launch(void* const* d_in, const int* in_sizes, int n_in,
                              void* d_out, int out_size)
{
    (void)in_sizes; (void)n_in; (void)out_size;
    const float* x  = (const float*)d_in[0];
    const float* qg = (const float*)d_in[1];
    const float* Wq = (const float*)d_in[2];
    const float* Wk = (const float*)d_in[3];
    const float* Wv = (const float*)d_in[4];
    const float* Wp = (const float*)d_in[5];
    float* out = (float*)d_out;

    float *qkv, *yp, *xr, *wqkv, *wp;
    cudaGetSymbolAddress((void**)&qkv, g_qkv);
    cudaGetSymbolAddress((void**)&yp, g_y);
    cudaGetSymbolAddress((void**)&xr, g_xr);
    cudaGetSymbolAddress((void**)&wqkv, g_wqkv);
    cudaGetSymbolAddress((void**)&wp, g_wp);

    // launch 1: all rounding + rope table
    prep_all<<<BL_X + BL_WQ + BL_WK + BL_WV + BL_WP + BL_TB, 256>>>(x, Wq, Wk, Wv, Wp);

    size_t gsm = 3 * (size_t)STAGE_B;  // 98304
    cudaFuncSetAttribute(gemm_hm, cudaFuncAttributeMaxDynamicSharedMemorySize, (int)gsm);

    // launch 2: fused QKV projection
    gemm_hm<<<dim3(QKVD / 128, BT / 128), 128, gsm>>>(xr, wqkv, qkv, QKVD, DIM);

    // launch 3: norm + rope + gain + tf32 rounding
    norm_rope2<<<(BT * 24) / 8, 256>>>(qg);

    // launch 4: flash attention (profiled slot)
    size_t asm_ = (size_t)(64 * 128 + 64 * KSTR + 64 * PSTR) * sizeof(float); // ~84KB
    cudaFuncSetAttribute(attn2, cudaFuncAttributeMaxDynamicSharedMemorySize, (int)asm_);
    attn2<<<dim3(SEQ / 64, BATCH * NHEADS), 128, asm_>>>();

    // launch 5: output projection
    gemm_hm<<<dim3(DIM / 128, BT / 128), 128, gsm>>>(yp, wp, out, DIM, DIM);
}

// round 6
// speedup vs baseline: 8.7712x; 2.0796x over previous
#include <cuda_runtime.h>
#include <cuda_fp16.h>
#include <math.h>
#include <float.h>
#include <stdint.h>

#define DIM 2048
#define QKVD 3072
#define NHEADS 16
#define NKV 4
#define HD 128
#define BATCH 2
#define SEQ 2048
#define BT (BATCH*SEQ)     // 4096
#define KVDIM 512

// Scratch (__device__ globals per allocation-free rule)
__device__ __align__(16) float  g_qkv[(size_t)BT*QKVD];    // gemm output (fp32)
__device__ __align__(16) __half g_qkvh[(size_t)BT*QKVD];   // normed/roped qkv (fp16)
__device__ __align__(16) __half g_xh[(size_t)BT*DIM];
__device__ __align__(16) __half g_wqkvh[(size_t)QKVD*DIM];
__device__ __align__(16) __half g_wph[(size_t)DIM*DIM];
__device__ __align__(16) __half g_yh[(size_t)BT*DIM];      // attention output (fp16)
__device__ __align__(16) float2 g_tab[SEQ*64];

// ---------------------------------------------------------------------------
// helpers
// ---------------------------------------------------------------------------
__device__ __forceinline__ uint32_t h2u(__half2 h) { return *(uint32_t*)&h; }
__device__ __forceinline__ uint32_t pack2(float a, float b) {
    __half2 h = __floats2half2_rn(a, b);
    return *(uint32_t*)&h;
}

__device__ __forceinline__ void mma_f16(float4& c, const uint32_t* a,
                                        uint32_t b0, uint32_t b1) {
    asm volatile(
        "mma.sync.aligned.m16n8k16.row.col.f32.f16.f16.f32 "
        "{%0,%1,%2,%3}, {%4,%5,%6,%7}, {%8,%9}, {%0,%1,%2,%3};"
        : "+f"(c.x), "+f"(c.y), "+f"(c.z), "+f"(c.w)
        : "r"(a[0]), "r"(a[1]), "r"(a[2]), "r"(a[3]), "r"(b0), "r"(b1));
}

__device__ __forceinline__ void cp_async16(uint32_t s, const void* g) {
    asm volatile("cp.async.ca.shared.global [%0], [%1], 16;" :: "r"(s), "l"(g));
}
__device__ __forceinline__ void cp_commit() {
    asm volatile("cp.async.commit_group;");
}
template<int N> __device__ __forceinline__ void cp_wait() {
    asm volatile("cp.async.wait_group %0;" :: "n"(N));
}

__device__ __forceinline__ uint32_t sm_u32(const void* p) {
    return (uint32_t)__cvta_generic_to_shared(p);
}

__device__ __forceinline__ void ldsm_x4(uint32_t* r, uint32_t addr) {
    asm volatile("ldmatrix.sync.aligned.m8n8.x4.shared.b16 {%0,%1,%2,%3}, [%4];"
                 : "=r"(r[0]), "=r"(r[1]), "=r"(r[2]), "=r"(r[3]) : "r"(addr));
}
__device__ __forceinline__ void ldsm_x4t(uint32_t* r, uint32_t addr) {
    asm volatile("ldmatrix.sync.aligned.m8n8.x4.trans.shared.b16 {%0,%1,%2,%3}, [%4];"
                 : "=r"(r[0]), "=r"(r[1]), "=r"(r[2]), "=r"(r[3]) : "r"(addr));
}

// swizzle a 16B-chunk index within a row (toggles low 3 bits only)
__device__ __forceinline__ uint32_t swz(uint32_t c, uint32_t r) {
    return (c & ~7u) | ((c ^ (r & 7u)) & 7u);
}

// ---------------------------------------------------------------------------
// prep_all: fp32 -> fp16 conversion of x + weights, plus RoPE table.
// Each conversion thread handles 8 elements.
// ---------------------------------------------------------------------------
#define BLH_X  4096
#define BLH_WQ 2048
#define BLH_WK 512
#define BLH_WV 512
#define BLH_WP 2048
#define BLH_TB 512

__global__ __launch_bounds__(256) void prep_all(const float* __restrict__ x,
                                                const float* __restrict__ Wq,
                                                const float* __restrict__ Wk,
                                                const float* __restrict__ Wv,
                                                const float* __restrict__ Wp)
{
    int blk = blockIdx.x;
    const float* src;
    __half* dst;
    if (blk < BLH_X)                  { src = x;  dst = g_xh; }
    else if ((blk -= BLH_X) < BLH_WQ) { src = Wq; dst = g_wqkvh; }
    else if ((blk -= BLH_WQ) < BLH_WK){ src = Wk; dst = g_wqkvh + (size_t)2048 * DIM; }
    else if ((blk -= BLH_WK) < BLH_WV){ src = Wv; dst = g_wqkvh + (size_t)2560 * DIM; }
    else if ((blk -= BLH_WV) < BLH_WP){ src = Wp; dst = g_wph; }
    else {
        blk -= BLH_WP;   // rope table
        int idx = blk * 256 + threadIdx.x;
        int t = idx >> 6, j = idx & 63;
        float inv_freq = expf(-(float)j * (9.210340371976184f / 64.0f));
        float ang = (float)t * inv_freq;
        float sn, cs;
        sincosf(ang, &sn, &cs);
        g_tab[idx] = make_float2(cs, sn);
        return;
    }
    int i = (blk * 256 + threadIdx.x) * 8;
    float4 v0 = *(const float4*)(src + i);
    float4 v1 = *(const float4*)(src + i + 4);
    uint4 o;
    o.x = pack2(v0.x, v0.y);
    o.y = pack2(v0.z, v0.w);
    o.z = pack2(v1.x, v1.y);
    o.w = pack2(v1.z, v1.w);
    *(uint4*)(dst + i) = o;
}

// ---------------------------------------------------------------------------
// warp-per-unit norm/rope: reads fp32 g_qkv, writes fp16 g_qkvh.
// units 0..15 q heads | 16..19 k heads | 20..23 v heads (convert only)
// ---------------------------------------------------------------------------
__global__ __launch_bounds__(256) void norm_rope2(const float* __restrict__ q_gain)
{
    int u = blockIdx.x * 8 + (threadIdx.x >> 5);
    int lane = threadIdx.x & 31;
    int row = u / 24;
    int h = u - row * 24;

    if (h >= 20) {
        const float* p = g_qkv + (size_t)row * QKVD + 2560 + (h - 20) * HD;
        __half* ph = g_qkvh + (size_t)row * QKVD + 2560 + (h - 20) * HD;
        ph[lane]      = __float2half_rn(p[lane]);
        ph[lane + 32] = __float2half_rn(p[lane + 32]);
        ph[lane + 64] = __float2half_rn(p[lane + 64]);
        ph[lane + 96] = __float2half_rn(p[lane + 96]);
        return;
    }

    const float* p;
    __half* ph;
    float g;
    if (h < NHEADS) {
        p = g_qkv + (size_t)row * QKVD + h * HD;
        ph = g_qkvh + (size_t)row * QKVD + h * HD;
        g = q_gain[h] * 0.08838834764831845f;  // fold 1/sqrt(128)
    } else {
        p = g_qkv + (size_t)row * QKVD + 2048 + (h - NHEADS) * HD;
        ph = g_qkvh + (size_t)row * QKVD + 2048 + (h - NHEADS) * HD;
        g = 1.0f;
    }

    float x1a = p[lane], x1b = p[lane + 32];
    float x2a = p[lane + 64], x2b = p[lane + 96];
    float ss = x1a * x1a + x1b * x1b + x2a * x2a + x2b * x2b;
#pragma unroll
    for (int o = 16; o; o >>= 1) ss += __shfl_xor_sync(0xffffffffu, ss, o);
    float r = rsqrtf(ss * (1.0f / 128.0f) + 1.1920928955078125e-07f);
    x1a *= r; x1b *= r; x2a *= r; x2b *= r;

    int t = row & (SEQ - 1);
    float2 csa = g_tab[t * 64 + lane];
    float2 csb = g_tab[t * 64 + lane + 32];

    ph[lane]      = __float2half_rn((x1a * csa.x + x2a * csa.y) * g);
    ph[lane + 64] = __float2half_rn((-x1a * csa.y + x2a * csa.x) * g);
    ph[lane + 32] = __float2half_rn((x1b * csb.x + x2b * csb.y) * g);
    ph[lane + 96] = __float2half_rn((-x1b * csb.y + x2b * csb.x) * g);
}

// ---------------------------------------------------------------------------
// fp16 HMMA GEMM: C[M,N](f32) = A[M,K](f16) @ B[N,K](f16)^T
// CTA tile 128x128x64, 128 threads (4 warps 2x2, warp tile 64x64).
// XOR-swizzled smem (32KB/stage fp16), 3-stage cp.async pipeline.
// ---------------------------------------------------------------------------
#define STAGE_B 32768

__global__ __launch_bounds__(128, 2) void gemm_h(const __half* __restrict__ A,
                                                 const __half* __restrict__ B,
                                                 float* __restrict__ C,
                                                 int N, int K)
{
    extern __shared__ __align__(16) char smem[];
    const int tid = threadIdx.x;
    const int wid = tid >> 5, lane = tid & 31;
    const int wm = wid >> 1, wn = wid & 1;
    const int gid = lane >> 2, tig = lane & 3;
    const int row0 = blockIdx.y * 128, col0 = blockIdx.x * 128;
    uint32_t sbase = sm_u32(smem);

    float4 acc[4][8];
#pragma unroll
    for (int i = 0; i < 4; i++)
#pragma unroll
        for (int j = 0; j < 8; j++) acc[i][j] = make_float4(0.f, 0.f, 0.f, 0.f);

    auto ld_tile = [&](int t, int s) {
        int k0 = t << 6;
        uint32_t sa = sbase + s * STAGE_B;
        uint32_t sb = sa + 16384;
        const __half* ga = A + (size_t)row0 * K + k0;
        const __half* gb = B + (size_t)col0 * K + k0;
#pragma unroll
        for (int i = 0; i < 8; i++) {
            int id = tid + i * 128;            // 0..1023
            int r = id >> 3, c = id & 7;       // row, 16B-chunk (8 halfs)
            uint32_t off = (uint32_t)(r * 128 + ((c ^ (r & 7)) << 4));
            cp_async16(sa + off, ga + (size_t)r * K + c * 8);
            cp_async16(sb + off, gb + (size_t)r * K + c * 8);
        }
        cp_commit();
    };

    const int lx = lane & 7;
    const int l15 = lane & 15;
    const int lb16 = (lane >> 4) & 1;
    const int lb8 = (lane >> 3) & 1;

    const int nT = K >> 6;   // 32
    ld_tile(0, 0);
    ld_tile(1, 1);

    for (int t = 0; t < nT; t++) {
        if (t + 1 < nT) cp_wait<1>(); else cp_wait<0>();
        __syncthreads();
        if (t + 2 < nT) ld_tile(t + 2, (t + 2) % 3);

        uint32_t sa = sbase + (t % 3) * STAGE_B;
        uint32_t sb = sa + 16384;
#pragma unroll
        for (int ks = 0; ks < 4; ks++) {
            uint32_t a[4][4], b[4][4];
#pragma unroll
            for (int mt = 0; mt < 4; mt++) {
                int row = wm * 64 + mt * 16 + l15;
                uint32_t chunk = (uint32_t)(2 * ks + lb16);
                ldsm_x4(a[mt], sa + (uint32_t)(row * 128)
                               + (((chunk ^ (row & 7)) & 7) << 4));
            }
#pragma unroll
            for (int nb = 0; nb < 4; nb++) {
                int row = wn * 64 + nb * 16 + lb16 * 8 + lx;
                uint32_t chunk = (uint32_t)(2 * ks + lb8);
                ldsm_x4(b[nb], sb + (uint32_t)(row * 128)
                               + (((chunk ^ (row & 7)) & 7) << 4));
            }
#pragma unroll
            for (int mt = 0; mt < 4; mt++)
#pragma unroll
                for (int nb = 0; nb < 4; nb++) {
                    mma_f16(acc[mt][2*nb],     a[mt], b[nb][0], b[nb][1]);
                    mma_f16(acc[mt][2*nb + 1], a[mt], b[nb][2], b[nb][3]);
                }
        }
    }

#pragma unroll
    for (int mt = 0; mt < 4; mt++) {
        int r = row0 + wm * 64 + mt * 16 + gid;
#pragma unroll
        for (int nt = 0; nt < 8; nt++) {
            int c = col0 + wn * 64 + nt * 8 + tig * 2;
            *(float2*)&C[(size_t)r * N + c]       = make_float2(acc[mt][nt].x, acc[mt][nt].y);
            *(float2*)&C[(size_t)(r + 8) * N + c] = make_float2(acc[mt][nt].z, acc[mt][nt].w);
        }
    }
}

// ---------------------------------------------------------------------------
// fp16 flash attention. 128 threads / 4 warps, 64 q-rows (16/warp), d=128.
// Q fragments persistent in regs; K/V fp16 tiles (16KB each) via phase-shifted
// cp.async prefetch; P stays in registers (C-frag == A-frag layout for fp16).
// V^T fragments via ldmatrix.x4.trans. fp32 accumulate everywhere.
// ---------------------------------------------------------------------------
__global__ __launch_bounds__(128) void attn3()
{
    extern __shared__ __align__(16) char smem[];
    uint32_t sKu = sm_u32(smem);           // 64 rows x 256B (swizzled)
    uint32_t sVu = sKu + 16384;            // 64 rows x 256B (swizzled)

    const int tid = threadIdx.x;
    const int wid = tid >> 5, lane = tid & 31;
    const int gid = lane >> 2, tig = lane & 3;
    const int qt = gridDim.x - 1 - blockIdx.x;   // big tiles first
    const int bh = blockIdx.y;
    const int b = bh >> 4, h = bh & 15, kvh = h >> 2;
    const int qb = qt * 64;

    const int lx = lane & 7;
    const int lb16 = (lane >> 4) & 1;
    const int lb8 = (lane >> 3) & 1;

    const __half* Kg0 = g_qkvh + (size_t)(b * SEQ) * QKVD + 2048 + kvh * HD;
    const __half* Vg0 = Kg0 + 512;

    // persistent Q fragments: 8 k-steps (k16), 4 regs each
    uint32_t qf[8][4];
    {
        const __half* Qg = g_qkvh + (size_t)(b * SEQ + qb + wid * 16) * QKVD + h * HD;
#pragma unroll
        for (int ks = 0; ks < 8; ks++) {
            qf[ks][0] = *(const uint32_t*)&Qg[(size_t)gid * QKVD + 16 * ks + 2 * tig];
            qf[ks][1] = *(const uint32_t*)&Qg[(size_t)(gid + 8) * QKVD + 16 * ks + 2 * tig];
            qf[ks][2] = *(const uint32_t*)&Qg[(size_t)gid * QKVD + 16 * ks + 8 + 2 * tig];
            qf[ks][3] = *(const uint32_t*)&Qg[(size_t)(gid + 8) * QKVD + 16 * ks + 8 + 2 * tig];
        }
    }

    auto ld_K = [&](int kt) {
        const __half* Kg = Kg0 + (size_t)(kt * 64) * QKVD;
#pragma unroll
        for (int i = 0; i < 8; i++) {
            int id = tid + i * 128;            // 0..1023
            int r = id >> 4, c = id & 15;      // row, 16B-chunk
            cp_async16(sKu + (uint32_t)(r * 256) + (swz(c, r) << 4),
                       Kg + (size_t)r * QKVD + c * 8);
        }
        cp_commit();
    };
    auto ld_V = [&](int kt) {
        const __half* Vg = Vg0 + (size_t)(kt * 64) * QKVD;
#pragma unroll
        for (int i = 0; i < 8; i++) {
            int id = tid + i * 128;
            int r = id >> 4, c = id & 15;
            cp_async16(sVu + (uint32_t)(r * 256) + (swz(c, r) << 4),
                       Vg + (size_t)r * QKVD + c * 8);
        }
        cp_commit();
    };

    float4 of[16];
#pragma unroll
    for (int i = 0; i < 16; i++) of[i] = make_float4(0.f, 0.f, 0.f, 0.f);
    float m0 = -FLT_MAX, m1 = -FLT_MAX, l0 = 0.f, l1 = 0.f;

    ld_K(0);
    ld_V(0);

    for (int kt = 0; kt <= qt; kt++) {
        const int kbase = kt * 64;
        const int ktn = (kt + 1 <= qt) ? kt + 1 : qt;

        cp_wait<1>();            // K[kt] ready (V[kt] pending)
        __syncthreads();

        // S = Q K^T : B-frags from K (rows = token, k = d)
        float4 s[8];
#pragma unroll
        for (int nt = 0; nt < 8; nt++) s[nt] = make_float4(0.f, 0.f, 0.f, 0.f);
#pragma unroll
        for (int nb = 0; nb < 4; nb++) {
            const int row = nb * 16 + lb16 * 8 + lx;
            const uint32_t ra = sKu + (uint32_t)(row * 256);
#pragma unroll
            for (int ks = 0; ks < 8; ks++) {
                uint32_t kb[4];
                uint32_t chunk = (uint32_t)(2 * ks + lb8);
                ldsm_x4(kb, ra + (swz(chunk, row) << 4));
                mma_f16(s[2*nb],     qf[ks], kb[0], kb[1]);
                mma_f16(s[2*nb + 1], qf[ks], kb[2], kb[3]);
            }
        }
        __syncthreads();         // everyone done reading Ks
        ld_K(ktn);               // prefetch next K (overlaps softmax + PV)

        // causal mask on diagonal tile
        if (kt == qt) {
            int r0 = qb + wid * 16 + gid;
#pragma unroll
            for (int nt = 0; nt < 8; nt++) {
                int c = kbase + nt * 8 + 2 * tig;
                if (c > r0)         s[nt].x = -FLT_MAX;
                if (c + 1 > r0)     s[nt].y = -FLT_MAX;
                if (c > r0 + 8)     s[nt].z = -FLT_MAX;
                if (c + 1 > r0 + 8) s[nt].w = -FLT_MAX;
            }
        }

        // online softmax (rows gid, gid+8; 4 lanes/row)
        float mt0 = -FLT_MAX, mt1 = -FLT_MAX;
#pragma unroll
        for (int nt = 0; nt < 8; nt++) {
            mt0 = fmaxf(mt0, fmaxf(s[nt].x, s[nt].y));
            mt1 = fmaxf(mt1, fmaxf(s[nt].z, s[nt].w));
        }
        mt0 = fmaxf(mt0, __shfl_xor_sync(0xffffffffu, mt0, 1));
        mt0 = fmaxf(mt0, __shfl_xor_sync(0xffffffffu, mt0, 2));
        mt1 = fmaxf(mt1, __shfl_xor_sync(0xffffffffu, mt1, 1));
        mt1 = fmaxf(mt1, __shfl_xor_sync(0xffffffffu, mt1, 2));

        float mn0 = fmaxf(m0, mt0), mn1 = fmaxf(m1, mt1);
        float a0 = __expf(m0 - mn0), a1 = __expf(m1 - mn1);
        float sum0 = 0.f, sum1 = 0.f;
#pragma unroll
        for (int nt = 0; nt < 8; nt++) {
            s[nt].x = __expf(s[nt].x - mn0);
            s[nt].y = __expf(s[nt].y - mn0);
            s[nt].z = __expf(s[nt].z - mn1);
            s[nt].w = __expf(s[nt].w - mn1);
            sum0 += s[nt].x + s[nt].y;
            sum1 += s[nt].z + s[nt].w;
        }
        sum0 += __shfl_xor_sync(0xffffffffu, sum0, 1);
        sum0 += __shfl_xor_sync(0xffffffffu, sum0, 2);
        sum1 += __shfl_xor_sync(0xffffffffu, sum1, 1);
        sum1 += __shfl_xor_sync(0xffffffffu, sum1, 2);

        l0 = l0 * a0 + sum0;
        l1 = l1 * a1 + sum1;
        m0 = mn0; m1 = mn1;
#pragma unroll
        for (int dt = 0; dt < 16; dt++) {
            of[dt].x *= a0; of[dt].y *= a0;
            of[dt].z *= a1; of[dt].w *= a1;
        }

        // P: fp32 C-frags -> fp16 A-frags, pure register conversion
        uint32_t ph[4][4];
#pragma unroll
        for (int kv = 0; kv < 4; kv++) {
            ph[kv][0] = pack2(s[2*kv].x,     s[2*kv].y);
            ph[kv][1] = pack2(s[2*kv].z,     s[2*kv].w);
            ph[kv][2] = pack2(s[2*kv + 1].x, s[2*kv + 1].y);
            ph[kv][3] = pack2(s[2*kv + 1].z, s[2*kv + 1].w);
        }

        cp_wait<1>();            // V[kt] ready (next K pending)
        __syncthreads();

        // O += P V : B-frags = V^T via ldmatrix.trans (rows = token, cols = d)
#pragma unroll
        for (int nb = 0; nb < 8; nb++) {
#pragma unroll
            for (int kv = 0; kv < 4; kv++) {
                const int row = kv * 16 + lb8 * 8 + lx;
                uint32_t chunk = (uint32_t)(2 * nb + lb16);
                uint32_t vb[4];
                ldsm_x4t(vb, sVu + (uint32_t)(row * 256) + (swz(chunk, row) << 4));
                mma_f16(of[2*nb],     ph[kv], vb[0], vb[1]);
                mma_f16(of[2*nb + 1], ph[kv], vb[2], vb[3]);
            }
        }
        __syncthreads();         // everyone done reading Vs
        ld_V(ktn);               // prefetch next V (overlaps next S)
    }
    cp_wait<0>();

    // epilogue: normalize, convert fp16, store y
    float inv0 = 1.0f / l0, inv1 = 1.0f / l1;
    __half* Yg = g_yh + (size_t)(b * SEQ + qb + wid * 16 + gid) * DIM + h * HD;
#pragma unroll
    for (int dt = 0; dt < 16; dt++) {
        int c = dt * 8 + 2 * tig;
        *(uint32_t*)&Yg[c]           = pack2(of[dt].x * inv0, of[dt].y * inv0);
        *(uint32_t*)&Yg[8 * DIM + c] = pack2(of[dt].z * inv1, of[dt].w * inv1);
    }
}

// ---------------------------------------------------------------------------
extern "C" void kernel_launch(void* const* d_in, const int* in_sizes, int n_in,
                              void* d_out, int out_size)
{
    (void)in_sizes; (void)n_in; (void)out_size;
    const float* x  = (const float*)d_in[0];
    const float* qg = (const float*)d_in[1];
    const float* Wq = (const float*)d_in[2];
    const float* Wk = (const float*)d_in[3];
    const float* Wv = (const float*)d_in[4];
    const float* Wp = (const float*)d_in[5];
    float* out = (float*)d_out;

    float *qkv;
    __half *xh, *wqkvh, *wph, *yh;
    cudaGetSymbolAddress((void**)&qkv, g_qkv);
    cudaGetSymbolAddress((void**)&xh, g_xh);
    cudaGetSymbolAddress((void**)&wqkvh, g_wqkvh);
    cudaGetSymbolAddress((void**)&wph, g_wph);
    cudaGetSymbolAddress((void**)&yh, g_yh);

    // launch 1: fp16 conversion + rope table
    prep_all<<<BLH_X + BLH_WQ + BLH_WK + BLH_WV + BLH_WP + BLH_TB, 256>>>(x, Wq, Wk, Wv, Wp);

    size_t gsm = 3 * (size_t)STAGE_B;  // 98304
    cudaFuncSetAttribute(gemm_h, cudaFuncAttributeMaxDynamicSharedMemorySize, (int)gsm);

    // launch 2: fused QKV projection (fp16 in, fp32 out)
    gemm_h<<<dim3(QKVD / 128, BT / 128), 128, gsm>>>(xh, wqkvh, qkv, QKVD, DIM);

    // launch 3: norm + rope + gain, fp32 -> fp16
    norm_rope2<<<(BT * 24) / 8, 256>>>(qg);

    // launch 4: flash attention (profiled slot)
    size_t asm_ = 32768;
    cudaFuncSetAttribute(attn3, cudaFuncAttributeMaxDynamicSharedMemorySize, (int)asm_);
    attn3<<<dim3(SEQ / 64, BATCH * NHEADS), 128, asm_>>>();

    // launch 5: output projection
    gemm_h<<<dim3(DIM / 128, BT / 128), 128, gsm>>>(yh, wph, out, DIM, DIM);
}